// round 11
// baseline (speedup 1.0000x reference)
#include <cuda_runtime.h>
#include <cuda_bf16.h>
#include <math.h>

typedef unsigned long long ull;

// Problem constants
#define BB 1
#define CC 32
#define HH 128
#define WW 160
#define DD 48
#define HW (HH*WW)          // 20480

// Padded per-(dz,dy) partial volumes U: (9, D+2, H+2, W) — no w halo (dx folded)
#define PD (DD+2)           // 50
#define PH (HH+2)           // 130
#define ROWS   160
#define SLICE  (PH*ROWS)    // 20800
#define CSTS   (PD*SLICE)   // 1,040,000 per volume

// Device globals zero-initialized at module load; halo cells of g_S are never
// written, so SAME-padding zeros in d/h are free and persistent.
__device__ float g_rot[2][9];
__device__ float g_trans[2][3];
__device__ float g_featT[3][HW*CC];          // (view, y, x, c) channel-last
__device__ float g_S[9u*CSTS];               // 9 padded partial volumes ~37MB
__device__ float g_cost[DD*HW];              // ~3.9 MB

#define FFMA2(d, a, b, c) \
    asm("fma.rn.f32x2 %0, %1, %2, %3;" : "=l"(d) : "l"(a), "l"(b), "l"(c))
#define PACK2(out, lo, hi) \
    asm("mov.b64 %0, {%1, %2};" : "=l"(out) : "f"(lo), "f"(hi))
#define UNPACK2(lo, hi, in) \
    asm("mov.b64 {%0, %1}, %2;" : "=f"(lo), "=f"(hi) : "l"(in))

// Dynamic smem layout (bytes):
//  Region A (union, temporally disjoint):
//    Phase A/B: s_wgt float4[2rows][2views][160] @0      (10240)
//               s_adr int4  [2][2][160]          @10240  (10240)
//    Phase D:   s_e0 float[2][9][162]            @0      (11664)
//               s_e2 float[2][9][162]            @11664  (11664)
//  s_var float[2][160][36]  @23328  (46080)   (w*144B -> 16B aligned)
//  s_pwt ull[27*16]         @69408  (3456)
#define OFF_WGT 0
#define OFF_ADR 10240
#define OFF_E0  0
#define OFF_E2  11664
#define OFF_VAR 23328
#define OFF_PWT 69408
#define SMEM_BYTES 72864

// ---------------------------------------------------------------------------
// Stage 0: proj_v @ inv(proj_ref) -> rot(3x3), trans(3) for views 1,2
// ---------------------------------------------------------------------------
__global__ void prep_kernel(const float* __restrict__ proj)
{
    if (threadIdx.x != 0 || blockIdx.x != 0) return;
    float A0[9], b0[3];
    for (int r = 0; r < 3; ++r) {
        for (int c = 0; c < 3; ++c) A0[r*3+c] = proj[r*4+c];
        b0[r] = proj[r*4+3];
    }
    float inv[9];
    inv[0] =  A0[4]*A0[8] - A0[5]*A0[7];
    inv[1] = -(A0[1]*A0[8] - A0[2]*A0[7]);
    inv[2] =  A0[1]*A0[5] - A0[2]*A0[4];
    inv[3] = -(A0[3]*A0[8] - A0[5]*A0[6]);
    inv[4] =  A0[0]*A0[8] - A0[2]*A0[6];
    inv[5] = -(A0[0]*A0[5] - A0[2]*A0[3]);
    inv[6] =  A0[3]*A0[7] - A0[4]*A0[6];
    inv[7] = -(A0[0]*A0[7] - A0[1]*A0[6]);
    inv[8] =  A0[0]*A0[4] - A0[1]*A0[3];
    float det = A0[0]*inv[0] + A0[1]*inv[3] + A0[2]*inv[6];
    float idet = 1.0f / det;
    for (int i = 0; i < 9; ++i) inv[i] *= idet;

    for (int v = 1; v < 3; ++v) {
        const float* P = proj + v*16;
        float Av[9], bv[3];
        for (int r = 0; r < 3; ++r) {
            for (int c = 0; c < 3; ++c) Av[r*3+c] = P[r*4+c];
            bv[r] = P[r*4+3];
        }
        float rot[9];
        for (int r = 0; r < 3; ++r)
            for (int c = 0; c < 3; ++c)
                rot[r*3+c] = Av[r*3+0]*inv[0*3+c] + Av[r*3+1]*inv[1*3+c] + Av[r*3+2]*inv[2*3+c];
        for (int r = 0; r < 3; ++r)
            g_trans[v-1][r] = bv[r] - (rot[r*3+0]*b0[0] + rot[r*3+1]*b0[1] + rot[r*3+2]*b0[2]);
        for (int i = 0; i < 9; ++i) g_rot[v-1][i] = rot[i];
    }
}

// ---------------------------------------------------------------------------
// Stage 1: tiled transpose (C,H,W) -> (H,W,C) for all 3 views.
// ---------------------------------------------------------------------------
__global__ void transpose_kernel(const float* __restrict__ f0,
                                 const float* __restrict__ f1,
                                 const float* __restrict__ f2)
{
    __shared__ float t[32][33];
    int v  = blockIdx.y;
    int p0 = blockIdx.x * 32;
    int tx = threadIdx.x, ty = threadIdx.y;
    const float* src = (v == 0) ? f0 : (v == 1) ? f1 : f2;

#pragma unroll
    for (int j = ty; j < 32; j += 8)
        t[j][tx] = src[j*HW + p0 + tx];
    __syncthreads();
#pragma unroll
    for (int j = ty; j < 32; j += 8)
        g_featT[v][(p0 + j)*CC + tx] = t[tx][j];
}

// ---------------------------------------------------------------------------
// Stage 2: warp + variance + fused channel GEMM + dx-fold, DUAL depth rows.
// Block per (h, d-pair), 256 threads, ~71KB smem -> 2 blocks/SM.
//  A: bilinear weights + addresses for 2 rows x 2 views x 160 w.
//  B: half-warp = voxel, lane = channel pair: LDG.64 corner gathers; ref
//     features loaded once, reused for both depth rows.
//  D: thread = w: weights loaded ONCE per k and applied to BOTH rows
//     (weight LDS halved); dx-folded into 9 U values per row via smem edges.
// ---------------------------------------------------------------------------
__global__ void __launch_bounds__(256, 2)
warp_var_kernel(const float* __restrict__ depth_values,
                const float* __restrict__ w_reg)
{
    extern __shared__ char smraw[];
    float4* s_wgt = (float4*)(smraw + OFF_WGT);   // [(r*2+v)*160 + w]
    int4*   s_adr = (int4*)  (smraw + OFF_ADR);
    float*  s_var = (float*) (smraw + OFF_VAR);   // r*5760 + w*36 + c
    ull*    s_pwt = (ull*)   (smraw + OFF_PWT);   // k*16 + c2
    float*  s_e0  = (float*) (smraw + OFF_E0);    // (r*9+k9)*162 + idx
    float*  s_e2  = (float*) (smraw + OFF_E2);

    int h  = blockIdx.x;
    int d0 = blockIdx.y * 2;
    int tid = threadIdx.x;

    // ---- Phase A: projection coords for 2 rows x 2 views x 160 w ----
    for (int t = tid; t < 640; t += 256) {
        int r   = t / 320;
        int rem = t - r*320;
        int v   = rem / 160;
        int w   = rem - v*160;
        float depth = __ldg(depth_values + d0 + r);
        float fx = (float)w, fy = (float)h;

        float px = (g_rot[v][0]*fx + g_rot[v][1]*fy + g_rot[v][2]) * depth + g_trans[v][0];
        float py = (g_rot[v][3]*fx + g_rot[v][4]*fy + g_rot[v][5]) * depth + g_trans[v][1];
        float pz = (g_rot[v][6]*fx + g_rot[v][7]*fy + g_rot[v][8]) * depth + g_trans[v][2];
        float gx = px / pz;
        float gy = py / pz;

        float x0f = floorf(gx), y0f = floorf(gy);
        float wx = gx - x0f, wy = gy - y0f;
        float x1f = x0f + 1.0f, y1f = y0f + 1.0f;

        float vx0 = (x0f >= 0.0f && x0f <= (float)(WW-1)) ? 1.0f : 0.0f;
        float vx1 = (x1f >= 0.0f && x1f <= (float)(WW-1)) ? 1.0f : 0.0f;
        float vy0 = (y0f >= 0.0f && y0f <= (float)(HH-1)) ? 1.0f : 0.0f;
        float vy1 = (y1f >= 0.0f && y1f <= (float)(HH-1)) ? 1.0f : 0.0f;

        float w00 = (1.0f-wx)*(1.0f-wy) * (vx0*vy0);
        float w10 = wx*(1.0f-wy)        * (vx1*vy0);
        float w01 = (1.0f-wx)*wy        * (vx0*vy1);
        float w11 = wx*wy               * (vx1*vy1);

        int x0 = (int)fminf(fmaxf(x0f, 0.0f), (float)(WW-1));
        int x1 = (int)fminf(fmaxf(x1f, 0.0f), (float)(WW-1));
        int y0 = (int)fminf(fmaxf(y0f, 0.0f), (float)(HH-1));
        int y1 = (int)fminf(fmaxf(y1f, 0.0f), (float)(HH-1));

        int si = (r*2 + v)*160 + w;
        s_wgt[si] = make_float4(w00, w10, w01, w11);
        s_adr[si] = make_int4((y0*WW + x0)*16, (y0*WW + x1)*16,
                              (y1*WW + x0)*16, (y1*WW + x1)*16);
    }

    // Packed weights: s_pwt[k*16+c2] = (wt[2c2][k], wt[2c2+1][k])
    for (int i = tid; i < 27*16; i += 256) {
        int k  = i >> 4;
        int c2 = i & 15;
        float lo = __ldg(w_reg + (2*c2    )*27 + k);
        float hi = __ldg(w_reg + (2*c2 + 1)*27 + k);
        ull p; PACK2(p, lo, hi);
        s_pwt[i] = p;
    }
    __syncthreads();

    // ---- Phase B: paired-voxel float2 gathers + variance, both rows ----
    {
        int lane = tid & 31;
        int warp = tid >> 5;
        int half = lane >> 4;          // which voxel of the pair
        int c2   = lane & 15;          // channel pair index

        const float2* F0 = (const float2*)g_featT[0];
        const float2* F1 = (const float2*)g_featT[1];
        const float2* F2 = (const float2*)g_featT[2];

        // ref features: d-independent, load once for both rows
        float2 refs[10];
#pragma unroll
        for (int i = 0; i < 10; ++i) {
            int w = warp*20 + 2*i + half;
            refs[i] = __ldg(F0 + (h*WW + w)*16 + c2);
        }

#pragma unroll
        for (int r = 0; r < 2; ++r) {
            const float4* wgt = s_wgt + (r*2)*160;
            const int4*   adr = s_adr + (r*2)*160;
            float* vr = s_var + r*5760;
#pragma unroll 5
            for (int i = 0; i < 10; ++i) {
                int w = warp*20 + 2*i + half;

                float2 ref = refs[i];
                float sx = ref.x, sy = ref.y;
                float qx = ref.x*ref.x, qy = ref.y*ref.y;

                {
                    float4 wt = wgt[w];
                    int4   ad = adr[w];
                    float2 a = __ldg(F1 + ad.x + c2);
                    float2 b = __ldg(F1 + ad.y + c2);
                    float2 c = __ldg(F1 + ad.z + c2);
                    float2 e = __ldg(F1 + ad.w + c2);
                    float fxv = wt.x*a.x + wt.y*b.x + wt.z*c.x + wt.w*e.x;
                    float fyv = wt.x*a.y + wt.y*b.y + wt.z*c.y + wt.w*e.y;
                    sx += fxv; qx += fxv*fxv;
                    sy += fyv; qy += fyv*fyv;
                }
                {
                    float4 wt = wgt[160 + w];
                    int4   ad = adr[160 + w];
                    float2 a = __ldg(F2 + ad.x + c2);
                    float2 b = __ldg(F2 + ad.y + c2);
                    float2 c = __ldg(F2 + ad.z + c2);
                    float2 e = __ldg(F2 + ad.w + c2);
                    float fxv = wt.x*a.x + wt.y*b.x + wt.z*c.x + wt.w*e.x;
                    float fyv = wt.x*a.y + wt.y*b.y + wt.z*c.y + wt.w*e.y;
                    sx += fxv; qx += fxv*fxv;
                    sy += fyv; qy += fyv*fyv;
                }

                const float inv3 = (1.0f/3.0f);
                float mx = sx * inv3, my = sy * inv3;
                float2 var = make_float2(qx*inv3 - mx*mx, qy*inv3 - my*my);
                *(float2*)(vr + w*36 + 2*c2) = var;
            }
        }
    }
    __syncthreads();   // after this, s_wgt/s_adr are dead -> region becomes edges

    // zero fold-edge boundary cells (2 rows x 9 x 2 edges)
    if (tid < 36) {
        int r  = tid / 18;
        int q  = tid - r*18;
        int a  = q / 9;
        int k9 = q - a*9;
        if (a) s_e2[(r*9 + k9)*162 + 160] = 0.0f;
        else   s_e0[(r*9 + k9)*162 + 0]   = 0.0f;
    }

    // ---- Phase D: dual-row channel GEMM (weights loaded once per k) ----
    float S1a[9], S1b[9];
    if (tid < WW) {
        int w = tid;
        ull va[16], vb[16];
        const ulonglong2* qa = (const ulonglong2*)(s_var + w*36);
        const ulonglong2* qb = (const ulonglong2*)(s_var + 5760 + w*36);
#pragma unroll
        for (int j = 0; j < 8; ++j) {
            ulonglong2 pa = qa[j], pb = qb[j];
            va[2*j] = pa.x; va[2*j+1] = pa.y;
            vb[2*j] = pb.x; vb[2*j+1] = pb.y;
        }

#pragma unroll
        for (int k = 0; k < 27; ++k) {
            const ulonglong2* pw = (const ulonglong2*)(s_pwt + k*16);
            ull aA = 0ull, aB = 0ull, bA = 0ull, bB = 0ull;
#pragma unroll
            for (int c2 = 0; c2 < 8; ++c2) {
                ulonglong2 wp = pw[c2];
                FFMA2(aA, va[2*c2],   wp.x, aA);
                FFMA2(aB, va[2*c2+1], wp.y, aB);
                FFMA2(bA, vb[2*c2],   wp.x, bA);
                FFMA2(bB, vb[2*c2+1], wp.y, bB);
            }
            float x0, x1, y0, y1;
            UNPACK2(x0, x1, aA); UNPACK2(y0, y1, aB);
            float Sa = (x0 + x1) + (y0 + y1);
            UNPACK2(x0, x1, bA); UNPACK2(y0, y1, bB);
            float Sb = (x0 + x1) + (y0 + y1);

            int k9 = k / 3, dx = k - k9*3;
            if (dx == 0) {
                s_e0[(0*9 + k9)*162 + w + 1] = Sa;
                s_e0[(1*9 + k9)*162 + w + 1] = Sb;
            } else if (dx == 1) {
                S1a[k9] = Sa; S1b[k9] = Sb;
            } else {
                s_e2[(0*9 + k9)*162 + w] = Sa;
                s_e2[(1*9 + k9)*162 + w] = Sb;
            }
        }
    }
    __syncthreads();

    if (tid < WW) {
        int w = tid;
        size_t base = (size_t)(d0 + 1)*SLICE + (h + 1)*ROWS + w;
#pragma unroll
        for (int k9 = 0; k9 < 9; ++k9) {
            float Ua = s_e0[(0*9 + k9)*162 + w] + S1a[k9] + s_e2[(0*9 + k9)*162 + w + 1];
            float Ub = s_e0[(1*9 + k9)*162 + w] + S1b[k9] + s_e2[(1*9 + k9)*162 + w + 1];
            g_S[(size_t)k9*CSTS + base]         = Ua;
            g_S[(size_t)k9*CSTS + base + SLICE] = Ub;
        }
    }
}

// ---------------------------------------------------------------------------
// Stage 3: 9-tap shifted-sum of partial volumes -> cost, float4-vectorized.
// cost(d,h,w) = sum_{dz,dy} U_{dz,dy}(padded d+dz, h+dy, w)
// ---------------------------------------------------------------------------
__global__ void __launch_bounds__(256)
sum_kernel()
{
    int idx = blockIdx.x * 256 + threadIdx.x;      // DD*HH*WW/4 = 245760
    int w4 = idx % 40;
    int t  = idx / 40;
    int h  = t % HH;
    int d  = t / HH;

    const float* base = g_S + (size_t)d*SLICE + h*ROWS + w4*4;
    float ax = 0.0f, ay = 0.0f, az = 0.0f, aw = 0.0f;
#pragma unroll
    for (int k9 = 0; k9 < 9; ++k9) {
        int dz = k9 / 3, dy = k9 - dz*3;
        float4 v = *(const float4*)(base + (size_t)k9*CSTS + dz*SLICE + dy*ROWS);
        ax += v.x; ay += v.y; az += v.z; aw += v.w;
    }
    *(float4*)(g_cost + d*HW + h*WW + w4*4) = make_float4(ax, ay, az, aw);
}

// ---------------------------------------------------------------------------
// Stage 4: softmax over D, expected depth + max-prob confidence.
// b_reg shifts all logits equally -> cancels in softmax -> ignored.
// ---------------------------------------------------------------------------
__global__ void __launch_bounds__(128)
depth_kernel(const float* __restrict__ depth_values, float* __restrict__ out)
{
    int pix = blockIdx.x * 128 + threadIdx.x;
    if (pix >= HW) return;

    float cv[DD];
    float m = -1e30f;
#pragma unroll
    for (int d = 0; d < DD; ++d) {
        cv[d] = g_cost[d*HW + pix];
        m = fmaxf(m, cv[d]);
    }
    float sum = 0.0f, dep = 0.0f, best = 0.0f;
#pragma unroll
    for (int d = 0; d < DD; ++d) {
        float e = expf(cv[d] - m);
        sum += e;
        dep += e * __ldg(depth_values + d);
        best = fmaxf(best, e);
    }
    float isum = 1.0f / sum;
    out[pix]      = dep * isum;
    out[HW + pix] = best * isum;
}

// ---------------------------------------------------------------------------
extern "C" void kernel_launch(void* const* d_in, const int* in_sizes, int n_in,
                              void* d_out, int out_size)
{
    const float* feat0 = (const float*)d_in[0];
    const float* feat1 = (const float*)d_in[1];
    const float* feat2 = (const float*)d_in[2];
    const float* proj  = (const float*)d_in[3];
    const float* dvals = (const float*)d_in[4];
    const float* wreg  = (const float*)d_in[5];
    float* out = (float*)d_out;

    cudaFuncSetAttribute(warp_var_kernel,
                         cudaFuncAttributeMaxDynamicSharedMemorySize, SMEM_BYTES);

    prep_kernel<<<1, 1>>>(proj);
    transpose_kernel<<<dim3(HW/32, 3), dim3(32, 8)>>>(feat0, feat1, feat2);
    warp_var_kernel<<<dim3(HH, DD/2), 256, SMEM_BYTES>>>(dvals, wreg);
    sum_kernel<<<(DD*HH*WW/4 + 255)/256, 256>>>();
    depth_kernel<<<(HW + 127)/128, 128>>>(dvals, out);
}

// round 12
// speedup vs baseline: 1.0498x; 1.0498x over previous
#include <cuda_runtime.h>
#include <cuda_bf16.h>
#include <math.h>

typedef unsigned long long ull;

// Problem constants
#define BB 1
#define CC 32
#define HH 128
#define WW 160
#define DD 48
#define HW (HH*WW)          // 20480

// Padded per-(dz,dy) partial volumes U: (9, D+2, H+2, W) — no w halo (dx folded)
#define PD (DD+2)           // 50
#define PH (HH+2)           // 130
#define ROWS   160
#define SLICE  (PH*ROWS)    // 20800
#define CSTS   (PD*SLICE)   // 1,040,000 per volume

// Device globals zero-initialized at module load; halo cells of g_S are never
// written, so SAME-padding zeros in d/h are free and persistent.
__device__ float g_rot[2][9];
__device__ float g_trans[2][3];
__device__ float g_featT[3][HW*CC];          // (view, y, x, c) channel-last
__device__ float g_S[9u*CSTS];               // 9 padded partial volumes ~37MB
__device__ float g_cost[DD*HW];              // ~3.9 MB

#define FFMA2(d, a, b, c) \
    asm("fma.rn.f32x2 %0, %1, %2, %3;" : "=l"(d) : "l"(a), "l"(b), "l"(c))
#define PACK2(out, lo, hi) \
    asm("mov.b64 %0, {%1, %2};" : "=l"(out) : "f"(lo), "f"(hi))
#define UNPACK2(lo, hi, in) \
    asm("mov.b64 {%0, %1}, %2;" : "=f"(lo), "=f"(hi) : "l"(in))

// Dynamic smem layout (bytes):
//  Region A (union, temporally disjoint):
//    Phase A/B: s_wgt float4[2rows][2views][160] @0      (10240)
//               s_adr int4  [2][2][160]          @10240  (10240)
//    Phase D:   s_e0 float[2][9][162]            @0      (11664)
//               s_e2 float[2][9][162]            @11664  (11664)
//  s_var float[2][160][36]  @23328  (46080)   (w*144B -> 16B aligned)
//  s_pwt ull[27*16]         @69408  (3456)
#define OFF_WGT 0
#define OFF_ADR 10240
#define OFF_E0  0
#define OFF_E2  11664
#define OFF_VAR 23328
#define OFF_PWT 69408
#define SMEM_BYTES 72864

// ---------------------------------------------------------------------------
// Stage 0: proj_v @ inv(proj_ref) -> rot(3x3), trans(3) for views 1,2
// ---------------------------------------------------------------------------
__global__ void prep_kernel(const float* __restrict__ proj)
{
    if (threadIdx.x != 0 || blockIdx.x != 0) return;
    float A0[9], b0[3];
    for (int r = 0; r < 3; ++r) {
        for (int c = 0; c < 3; ++c) A0[r*3+c] = proj[r*4+c];
        b0[r] = proj[r*4+3];
    }
    float inv[9];
    inv[0] =  A0[4]*A0[8] - A0[5]*A0[7];
    inv[1] = -(A0[1]*A0[8] - A0[2]*A0[7]);
    inv[2] =  A0[1]*A0[5] - A0[2]*A0[4];
    inv[3] = -(A0[3]*A0[8] - A0[5]*A0[6]);
    inv[4] =  A0[0]*A0[8] - A0[2]*A0[6];
    inv[5] = -(A0[0]*A0[5] - A0[2]*A0[3]);
    inv[6] =  A0[3]*A0[7] - A0[4]*A0[6];
    inv[7] = -(A0[0]*A0[7] - A0[1]*A0[6]);
    inv[8] =  A0[0]*A0[4] - A0[1]*A0[3];
    float det = A0[0]*inv[0] + A0[1]*inv[3] + A0[2]*inv[6];
    float idet = 1.0f / det;
    for (int i = 0; i < 9; ++i) inv[i] *= idet;

    for (int v = 1; v < 3; ++v) {
        const float* P = proj + v*16;
        float Av[9], bv[3];
        for (int r = 0; r < 3; ++r) {
            for (int c = 0; c < 3; ++c) Av[r*3+c] = P[r*4+c];
            bv[r] = P[r*4+3];
        }
        float rot[9];
        for (int r = 0; r < 3; ++r)
            for (int c = 0; c < 3; ++c)
                rot[r*3+c] = Av[r*3+0]*inv[0*3+c] + Av[r*3+1]*inv[1*3+c] + Av[r*3+2]*inv[2*3+c];
        for (int r = 0; r < 3; ++r)
            g_trans[v-1][r] = bv[r] - (rot[r*3+0]*b0[0] + rot[r*3+1]*b0[1] + rot[r*3+2]*b0[2]);
        for (int i = 0; i < 9; ++i) g_rot[v-1][i] = rot[i];
    }
}

// ---------------------------------------------------------------------------
// Stage 1: tiled transpose (C,H,W) -> (H,W,C) for all 3 views.
// ---------------------------------------------------------------------------
__global__ void transpose_kernel(const float* __restrict__ f0,
                                 const float* __restrict__ f1,
                                 const float* __restrict__ f2)
{
    __shared__ float t[32][33];
    int v  = blockIdx.y;
    int p0 = blockIdx.x * 32;
    int tx = threadIdx.x, ty = threadIdx.y;
    const float* src = (v == 0) ? f0 : (v == 1) ? f1 : f2;

#pragma unroll
    for (int j = ty; j < 32; j += 8)
        t[j][tx] = src[j*HW + p0 + tx];
    __syncthreads();
#pragma unroll
    for (int j = ty; j < 32; j += 8)
        g_featT[v][(p0 + j)*CC + tx] = t[tx][j];
}

// ---------------------------------------------------------------------------
// Stage 2: warp + variance + fused channel GEMM + dx-fold, DUAL depth rows.
// Block per (h, d-pair), 256 threads, ~71KB smem -> 2 blocks/SM.
//  A: bilinear weights + addresses for 2 rows x 2 views x 160 w.
//  B: half-warp = voxel, lane = channel pair: LDG.64 corner gathers; ref
//     features loaded once, reused for both depth rows.
//  D: thread = w: weights loaded ONCE per k and applied to BOTH rows
//     (weight LDS halved); dx-folded into 9 U values per row via smem edges.
// ---------------------------------------------------------------------------
__global__ void __launch_bounds__(256, 2)
warp_var_kernel(const float* __restrict__ depth_values,
                const float* __restrict__ w_reg)
{
    extern __shared__ char smraw[];
    float4* s_wgt = (float4*)(smraw + OFF_WGT);   // [(r*2+v)*160 + w]
    int4*   s_adr = (int4*)  (smraw + OFF_ADR);
    float*  s_var = (float*) (smraw + OFF_VAR);   // r*5760 + w*36 + c
    ull*    s_pwt = (ull*)   (smraw + OFF_PWT);   // k*16 + c2
    float*  s_e0  = (float*) (smraw + OFF_E0);    // (r*9+k9)*162 + idx
    float*  s_e2  = (float*) (smraw + OFF_E2);

    int h  = blockIdx.x;
    int d0 = blockIdx.y * 2;
    int tid = threadIdx.x;

    // ---- Phase A: projection coords for 2 rows x 2 views x 160 w ----
    for (int t = tid; t < 640; t += 256) {
        int r   = t / 320;
        int rem = t - r*320;
        int v   = rem / 160;
        int w   = rem - v*160;
        float depth = __ldg(depth_values + d0 + r);
        float fx = (float)w, fy = (float)h;

        float px = (g_rot[v][0]*fx + g_rot[v][1]*fy + g_rot[v][2]) * depth + g_trans[v][0];
        float py = (g_rot[v][3]*fx + g_rot[v][4]*fy + g_rot[v][5]) * depth + g_trans[v][1];
        float pz = (g_rot[v][6]*fx + g_rot[v][7]*fy + g_rot[v][8]) * depth + g_trans[v][2];
        float gx = px / pz;
        float gy = py / pz;

        float x0f = floorf(gx), y0f = floorf(gy);
        float wx = gx - x0f, wy = gy - y0f;
        float x1f = x0f + 1.0f, y1f = y0f + 1.0f;

        float vx0 = (x0f >= 0.0f && x0f <= (float)(WW-1)) ? 1.0f : 0.0f;
        float vx1 = (x1f >= 0.0f && x1f <= (float)(WW-1)) ? 1.0f : 0.0f;
        float vy0 = (y0f >= 0.0f && y0f <= (float)(HH-1)) ? 1.0f : 0.0f;
        float vy1 = (y1f >= 0.0f && y1f <= (float)(HH-1)) ? 1.0f : 0.0f;

        float w00 = (1.0f-wx)*(1.0f-wy) * (vx0*vy0);
        float w10 = wx*(1.0f-wy)        * (vx1*vy0);
        float w01 = (1.0f-wx)*wy        * (vx0*vy1);
        float w11 = wx*wy               * (vx1*vy1);

        int x0 = (int)fminf(fmaxf(x0f, 0.0f), (float)(WW-1));
        int x1 = (int)fminf(fmaxf(x1f, 0.0f), (float)(WW-1));
        int y0 = (int)fminf(fmaxf(y0f, 0.0f), (float)(HH-1));
        int y1 = (int)fminf(fmaxf(y1f, 0.0f), (float)(HH-1));

        int si = (r*2 + v)*160 + w;
        s_wgt[si] = make_float4(w00, w10, w01, w11);
        s_adr[si] = make_int4((y0*WW + x0)*16, (y0*WW + x1)*16,
                              (y1*WW + x0)*16, (y1*WW + x1)*16);
    }

    // Packed weights: s_pwt[k*16+c2] = (wt[2c2][k], wt[2c2+1][k])
    for (int i = tid; i < 27*16; i += 256) {
        int k  = i >> 4;
        int c2 = i & 15;
        float lo = __ldg(w_reg + (2*c2    )*27 + k);
        float hi = __ldg(w_reg + (2*c2 + 1)*27 + k);
        ull p; PACK2(p, lo, hi);
        s_pwt[i] = p;
    }
    __syncthreads();

    // ---- Phase B: paired-voxel float2 gathers + variance, both rows ----
    {
        int lane = tid & 31;
        int warp = tid >> 5;
        int half = lane >> 4;          // which voxel of the pair
        int c2   = lane & 15;          // channel pair index

        const float2* F0 = (const float2*)g_featT[0];
        const float2* F1 = (const float2*)g_featT[1];
        const float2* F2 = (const float2*)g_featT[2];

        // ref features: d-independent, load once for both rows
        float2 refs[10];
#pragma unroll
        for (int i = 0; i < 10; ++i) {
            int w = warp*20 + 2*i + half;
            refs[i] = __ldg(F0 + (h*WW + w)*16 + c2);
        }

#pragma unroll
        for (int r = 0; r < 2; ++r) {
            const float4* wgt = s_wgt + (r*2)*160;
            const int4*   adr = s_adr + (r*2)*160;
            float* vr = s_var + r*5760;
#pragma unroll 5
            for (int i = 0; i < 10; ++i) {
                int w = warp*20 + 2*i + half;

                float2 ref = refs[i];
                float sx = ref.x, sy = ref.y;
                float qx = ref.x*ref.x, qy = ref.y*ref.y;

                {
                    float4 wt = wgt[w];
                    int4   ad = adr[w];
                    float2 a = __ldg(F1 + ad.x + c2);
                    float2 b = __ldg(F1 + ad.y + c2);
                    float2 c = __ldg(F1 + ad.z + c2);
                    float2 e = __ldg(F1 + ad.w + c2);
                    float fxv = wt.x*a.x + wt.y*b.x + wt.z*c.x + wt.w*e.x;
                    float fyv = wt.x*a.y + wt.y*b.y + wt.z*c.y + wt.w*e.y;
                    sx += fxv; qx += fxv*fxv;
                    sy += fyv; qy += fyv*fyv;
                }
                {
                    float4 wt = wgt[160 + w];
                    int4   ad = adr[160 + w];
                    float2 a = __ldg(F2 + ad.x + c2);
                    float2 b = __ldg(F2 + ad.y + c2);
                    float2 c = __ldg(F2 + ad.z + c2);
                    float2 e = __ldg(F2 + ad.w + c2);
                    float fxv = wt.x*a.x + wt.y*b.x + wt.z*c.x + wt.w*e.x;
                    float fyv = wt.x*a.y + wt.y*b.y + wt.z*c.y + wt.w*e.y;
                    sx += fxv; qx += fxv*fxv;
                    sy += fyv; qy += fyv*fyv;
                }

                const float inv3 = (1.0f/3.0f);
                float mx = sx * inv3, my = sy * inv3;
                float2 var = make_float2(qx*inv3 - mx*mx, qy*inv3 - my*my);
                *(float2*)(vr + w*36 + 2*c2) = var;
            }
        }
    }
    __syncthreads();   // after this, s_wgt/s_adr are dead -> region becomes edges

    // zero fold-edge boundary cells (2 rows x 9 x 2 edges)
    if (tid < 36) {
        int r  = tid / 18;
        int q  = tid - r*18;
        int a  = q / 9;
        int k9 = q - a*9;
        if (a) s_e2[(r*9 + k9)*162 + 160] = 0.0f;
        else   s_e0[(r*9 + k9)*162 + 0]   = 0.0f;
    }

    // ---- Phase D: dual-row channel GEMM (weights loaded once per k) ----
    float S1a[9], S1b[9];
    if (tid < WW) {
        int w = tid;
        ull va[16], vb[16];
        const ulonglong2* qa = (const ulonglong2*)(s_var + w*36);
        const ulonglong2* qb = (const ulonglong2*)(s_var + 5760 + w*36);
#pragma unroll
        for (int j = 0; j < 8; ++j) {
            ulonglong2 pa = qa[j], pb = qb[j];
            va[2*j] = pa.x; va[2*j+1] = pa.y;
            vb[2*j] = pb.x; vb[2*j+1] = pb.y;
        }

#pragma unroll
        for (int k = 0; k < 27; ++k) {
            const ulonglong2* pw = (const ulonglong2*)(s_pwt + k*16);
            ull aA = 0ull, aB = 0ull, bA = 0ull, bB = 0ull;
#pragma unroll
            for (int c2 = 0; c2 < 8; ++c2) {
                ulonglong2 wp = pw[c2];
                FFMA2(aA, va[2*c2],   wp.x, aA);
                FFMA2(aB, va[2*c2+1], wp.y, aB);
                FFMA2(bA, vb[2*c2],   wp.x, bA);
                FFMA2(bB, vb[2*c2+1], wp.y, bB);
            }
            float x0, x1, y0, y1;
            UNPACK2(x0, x1, aA); UNPACK2(y0, y1, aB);
            float Sa = (x0 + x1) + (y0 + y1);
            UNPACK2(x0, x1, bA); UNPACK2(y0, y1, bB);
            float Sb = (x0 + x1) + (y0 + y1);

            int k9 = k / 3, dx = k - k9*3;
            if (dx == 0) {
                s_e0[(0*9 + k9)*162 + w + 1] = Sa;
                s_e0[(1*9 + k9)*162 + w + 1] = Sb;
            } else if (dx == 1) {
                S1a[k9] = Sa; S1b[k9] = Sb;
            } else {
                s_e2[(0*9 + k9)*162 + w] = Sa;
                s_e2[(1*9 + k9)*162 + w] = Sb;
            }
        }
    }
    __syncthreads();

    if (tid < WW) {
        int w = tid;
        size_t base = (size_t)(d0 + 1)*SLICE + (h + 1)*ROWS + w;
#pragma unroll
        for (int k9 = 0; k9 < 9; ++k9) {
            float Ua = s_e0[(0*9 + k9)*162 + w] + S1a[k9] + s_e2[(0*9 + k9)*162 + w + 1];
            float Ub = s_e0[(1*9 + k9)*162 + w] + S1b[k9] + s_e2[(1*9 + k9)*162 + w + 1];
            g_S[(size_t)k9*CSTS + base]         = Ua;
            g_S[(size_t)k9*CSTS + base + SLICE] = Ub;
        }
    }
}

// ---------------------------------------------------------------------------
// Stage 3: 9-tap shifted-sum of partial volumes -> cost, float4-vectorized.
// cost(d,h,w) = sum_{dz,dy} U_{dz,dy}(padded d+dz, h+dy, w)
// ---------------------------------------------------------------------------
__global__ void __launch_bounds__(256)
sum_kernel()
{
    int idx = blockIdx.x * 256 + threadIdx.x;      // DD*HH*WW/4 = 245760
    int w4 = idx % 40;
    int t  = idx / 40;
    int h  = t % HH;
    int d  = t / HH;

    const float* base = g_S + (size_t)d*SLICE + h*ROWS + w4*4;
    float ax = 0.0f, ay = 0.0f, az = 0.0f, aw = 0.0f;
#pragma unroll
    for (int k9 = 0; k9 < 9; ++k9) {
        int dz = k9 / 3, dy = k9 - dz*3;
        float4 v = *(const float4*)(base + (size_t)k9*CSTS + dz*SLICE + dy*ROWS);
        ax += v.x; ay += v.y; az += v.z; aw += v.w;
    }
    *(float4*)(g_cost + d*HW + h*WW + w4*4) = make_float4(ax, ay, az, aw);
}

// ---------------------------------------------------------------------------
// Stage 4: softmax over D, expected depth + max-prob confidence.
// b_reg shifts all logits equally -> cancels in softmax -> ignored.
// ---------------------------------------------------------------------------
__global__ void __launch_bounds__(128)
depth_kernel(const float* __restrict__ depth_values, float* __restrict__ out)
{
    int pix = blockIdx.x * 128 + threadIdx.x;
    if (pix >= HW) return;

    float cv[DD];
    float m = -1e30f;
#pragma unroll
    for (int d = 0; d < DD; ++d) {
        cv[d] = g_cost[d*HW + pix];
        m = fmaxf(m, cv[d]);
    }
    float sum = 0.0f, dep = 0.0f, best = 0.0f;
#pragma unroll
    for (int d = 0; d < DD; ++d) {
        float e = expf(cv[d] - m);
        sum += e;
        dep += e * __ldg(depth_values + d);
        best = fmaxf(best, e);
    }
    float isum = 1.0f / sum;
    out[pix]      = dep * isum;
    out[HW + pix] = best * isum;
}

// ---------------------------------------------------------------------------
extern "C" void kernel_launch(void* const* d_in, const int* in_sizes, int n_in,
                              void* d_out, int out_size)
{
    const float* feat0 = (const float*)d_in[0];
    const float* feat1 = (const float*)d_in[1];
    const float* feat2 = (const float*)d_in[2];
    const float* proj  = (const float*)d_in[3];
    const float* dvals = (const float*)d_in[4];
    const float* wreg  = (const float*)d_in[5];
    float* out = (float*)d_out;

    cudaFuncSetAttribute(warp_var_kernel,
                         cudaFuncAttributeMaxDynamicSharedMemorySize, SMEM_BYTES);

    prep_kernel<<<1, 1>>>(proj);
    transpose_kernel<<<dim3(HW/32, 3), dim3(32, 8)>>>(feat0, feat1, feat2);
    warp_var_kernel<<<dim3(HH, DD/2), 256, SMEM_BYTES>>>(dvals, wreg);
    sum_kernel<<<(DD*HH*WW/4 + 255)/256, 256>>>();
    depth_kernel<<<(HW + 127)/128, 128>>>(dvals, out);
}

// round 13
// speedup vs baseline: 1.1489x; 1.0944x over previous
#include <cuda_runtime.h>
#include <cuda_bf16.h>
#include <math.h>

typedef unsigned long long ull;

// Problem constants
#define BB 1
#define CC 32
#define HH 128
#define WW 160
#define DD 48
#define HW (HH*WW)          // 20480

// Padded per-(dz,dy) partial volumes U: (9, D+2, H+2, W) — no w halo (dx folded)
#define PD (DD+2)           // 50
#define PH (HH+2)           // 130
#define ROWS   160
#define SLICE  (PH*ROWS)    // 20800
#define CSTS   (PD*SLICE)   // 1,040,000 per volume

// Device globals zero-initialized at module load; halo cells of g_S are never
// written, so SAME-padding zeros in d/h are free and persistent.
__device__ float g_rot[2][9];
__device__ float g_trans[2][3];
__device__ float g_featT[3][HW*CC];          // (view, y, x, c) channel-last
__device__ float g_S[9u*CSTS];               // 9 padded partial volumes ~37MB

#define FFMA2(d, a, b, c) \
    asm("fma.rn.f32x2 %0, %1, %2, %3;" : "=l"(d) : "l"(a), "l"(b), "l"(c))
#define PACK2(out, lo, hi) \
    asm("mov.b64 %0, {%1, %2};" : "=l"(out) : "f"(lo), "f"(hi))
#define UNPACK2(lo, hi, in) \
    asm("mov.b64 {%0, %1}, %2;" : "=f"(lo), "=f"(hi) : "l"(in))

// Dynamic smem layout (bytes).  Region [0,11664) is a UNION:
//   Phase A/B: s_wgt float4[2][160] @0 (5120) | s_adr int4[2][160] @5120 (5120)
//   Phase D/E: s_e0 float[9][162] @0 (5832)   | s_e2 float[9][162] @5832 (5832)
// (wgt/adr are dead after the post-Phase-B sync; edges written after it.)
#define OFF_WGT 0
#define OFF_ADR 5120
#define OFF_E0  0
#define OFF_E2  5832
#define OFF_VAR 11664          // float [160][36]  (23040 B; w stride 144B)
#define OFF_PWT 34704          // ull [27*16]      (3456 B)
#define SMEM_BYTES 38160

// ---------------------------------------------------------------------------
// Stage 0: proj_v @ inv(proj_ref) -> rot(3x3), trans(3) for views 1,2
// ---------------------------------------------------------------------------
__global__ void prep_kernel(const float* __restrict__ proj)
{
    if (threadIdx.x != 0 || blockIdx.x != 0) return;
    float A0[9], b0[3];
    for (int r = 0; r < 3; ++r) {
        for (int c = 0; c < 3; ++c) A0[r*3+c] = proj[r*4+c];
        b0[r] = proj[r*4+3];
    }
    float inv[9];
    inv[0] =  A0[4]*A0[8] - A0[5]*A0[7];
    inv[1] = -(A0[1]*A0[8] - A0[2]*A0[7]);
    inv[2] =  A0[1]*A0[5] - A0[2]*A0[4];
    inv[3] = -(A0[3]*A0[8] - A0[5]*A0[6]);
    inv[4] =  A0[0]*A0[8] - A0[2]*A0[6];
    inv[5] = -(A0[0]*A0[5] - A0[2]*A0[3]);
    inv[6] =  A0[3]*A0[7] - A0[4]*A0[6];
    inv[7] = -(A0[0]*A0[7] - A0[1]*A0[6]);
    inv[8] =  A0[0]*A0[4] - A0[1]*A0[3];
    float det = A0[0]*inv[0] + A0[1]*inv[3] + A0[2]*inv[6];
    float idet = 1.0f / det;
    for (int i = 0; i < 9; ++i) inv[i] *= idet;

    for (int v = 1; v < 3; ++v) {
        const float* P = proj + v*16;
        float Av[9], bv[3];
        for (int r = 0; r < 3; ++r) {
            for (int c = 0; c < 3; ++c) Av[r*3+c] = P[r*4+c];
            bv[r] = P[r*4+3];
        }
        float rot[9];
        for (int r = 0; r < 3; ++r)
            for (int c = 0; c < 3; ++c)
                rot[r*3+c] = Av[r*3+0]*inv[0*3+c] + Av[r*3+1]*inv[1*3+c] + Av[r*3+2]*inv[2*3+c];
        for (int r = 0; r < 3; ++r)
            g_trans[v-1][r] = bv[r] - (rot[r*3+0]*b0[0] + rot[r*3+1]*b0[1] + rot[r*3+2]*b0[2]);
        for (int i = 0; i < 9; ++i) g_rot[v-1][i] = rot[i];
    }
}

// ---------------------------------------------------------------------------
// Stage 1: tiled transpose (C,H,W) -> (H,W,C) for all 3 views.
// ---------------------------------------------------------------------------
__global__ void transpose_kernel(const float* __restrict__ f0,
                                 const float* __restrict__ f1,
                                 const float* __restrict__ f2)
{
    __shared__ float t[32][33];
    int v  = blockIdx.y;
    int p0 = blockIdx.x * 32;
    int tx = threadIdx.x, ty = threadIdx.y;
    const float* src = (v == 0) ? f0 : (v == 1) ? f1 : f2;

#pragma unroll
    for (int j = ty; j < 32; j += 8)
        t[j][tx] = src[j*HW + p0 + tx];
    __syncthreads();
#pragma unroll
    for (int j = ty; j < 32; j += 8)
        g_featT[v][(p0 + j)*CC + tx] = t[tx][j];
}

// ---------------------------------------------------------------------------
// Stage 2: warp + variance + fused channel GEMM + dx-fold.
// Block per (d,h), 256 threads, 38.2KB smem -> 4-5 blocks/SM.
//  A: bilinear weights + pixel addresses (2 views x 160 w) + packed weights.
//  B: QUAD-voxel gathers: lane = (voxel-quarter, float4 channel group); every
//     corner load is one LDG.128 serving FOUR voxels (2.25 LDG/voxel).
//  D: thread = w: 27 FFMA2 dot products over 32 channels, dx-folded into 9
//     partial values U_{dz,dy} via smem edge rows; 9 stores per voxel.
// ---------------------------------------------------------------------------
__global__ void __launch_bounds__(256)
warp_var_kernel(const float* __restrict__ depth_values,
                const float* __restrict__ w_reg)
{
    extern __shared__ char smraw[];
    float4* s_wgt = (float4*)(smraw + OFF_WGT);   // [v*160 + w]
    int4*   s_adr = (int4*)  (smraw + OFF_ADR);   // pixel*8 (float4 index)
    float*  s_var = (float*) (smraw + OFF_VAR);   // w*36 + c
    ull*    s_pwt = (ull*)   (smraw + OFF_PWT);   // k*16 + c2
    float*  s_e0  = (float*) (smraw + OFF_E0);    // k9*162 + idx
    float*  s_e2  = (float*) (smraw + OFF_E2);

    int blk = blockIdx.x;                  // 0 .. DD*HH-1
    int d = blk / HH;
    int h = blk - d*HH;
    int tid = threadIdx.x;

    float depth = __ldg(depth_values + d);

    // ---- Phase A: projection coords per (view, w) ----
    for (int t = tid; t < 2*WW; t += 256) {
        int v = t / WW;
        int w = t - v*WW;
        float fx = (float)w, fy = (float)h;

        float px = (g_rot[v][0]*fx + g_rot[v][1]*fy + g_rot[v][2]) * depth + g_trans[v][0];
        float py = (g_rot[v][3]*fx + g_rot[v][4]*fy + g_rot[v][5]) * depth + g_trans[v][1];
        float pz = (g_rot[v][6]*fx + g_rot[v][7]*fy + g_rot[v][8]) * depth + g_trans[v][2];
        float gx = px / pz;
        float gy = py / pz;

        float x0f = floorf(gx), y0f = floorf(gy);
        float wx = gx - x0f, wy = gy - y0f;
        float x1f = x0f + 1.0f, y1f = y0f + 1.0f;

        float vx0 = (x0f >= 0.0f && x0f <= (float)(WW-1)) ? 1.0f : 0.0f;
        float vx1 = (x1f >= 0.0f && x1f <= (float)(WW-1)) ? 1.0f : 0.0f;
        float vy0 = (y0f >= 0.0f && y0f <= (float)(HH-1)) ? 1.0f : 0.0f;
        float vy1 = (y1f >= 0.0f && y1f <= (float)(HH-1)) ? 1.0f : 0.0f;

        float w00 = (1.0f-wx)*(1.0f-wy) * (vx0*vy0);
        float w10 = wx*(1.0f-wy)        * (vx1*vy0);
        float w01 = (1.0f-wx)*wy        * (vx0*vy1);
        float w11 = wx*wy               * (vx1*vy1);

        int x0 = (int)fminf(fmaxf(x0f, 0.0f), (float)(WW-1));
        int x1 = (int)fminf(fmaxf(x1f, 0.0f), (float)(WW-1));
        int y0 = (int)fminf(fmaxf(y0f, 0.0f), (float)(HH-1));
        int y1 = (int)fminf(fmaxf(y1f, 0.0f), (float)(HH-1));

        s_wgt[t] = make_float4(w00, w10, w01, w11);
        s_adr[t] = make_int4((y0*WW + x0)*8, (y0*WW + x1)*8,
                             (y1*WW + x0)*8, (y1*WW + x1)*8);
    }

    // Packed weights: s_pwt[k*16+c2] = (wt[2c2][k], wt[2c2+1][k])
    for (int i = tid; i < 27*16; i += 256) {
        int k  = i >> 4;
        int c2 = i & 15;
        float lo = __ldg(w_reg + (2*c2    )*27 + k);
        float hi = __ldg(w_reg + (2*c2 + 1)*27 + k);
        ull p; PACK2(p, lo, hi);
        s_pwt[i] = p;
    }
    __syncthreads();

    // ---- Phase B: quad-voxel float4 gathers + variance ----
    {
        int lane = tid & 31;
        int warp = tid >> 5;
        int qd   = lane >> 3;          // voxel within quad (0..3)
        int c4   = lane & 7;           // float4 channel group (0..7)

        const float4* F0 = (const float4*)g_featT[0];
        const float4* F1 = (const float4*)g_featT[1];
        const float4* F2 = (const float4*)g_featT[2];

#pragma unroll
        for (int i = 0; i < 5; ++i) {
            int w = warp*20 + i*4 + qd;

            float4 ref = __ldg(F0 + (h*WW + w)*8 + c4);
            float sx = ref.x, sy = ref.y, sz = ref.z, sw = ref.w;
            float qx = ref.x*ref.x, qy = ref.y*ref.y;
            float qz = ref.z*ref.z, qw = ref.w*ref.w;

            {
                float4 wt = s_wgt[w];
                int4   ad = s_adr[w];
                float4 a = __ldg(F1 + ad.x + c4);
                float4 b = __ldg(F1 + ad.y + c4);
                float4 c = __ldg(F1 + ad.z + c4);
                float4 e = __ldg(F1 + ad.w + c4);
                float f0v = wt.x*a.x + wt.y*b.x + wt.z*c.x + wt.w*e.x;
                float f1v = wt.x*a.y + wt.y*b.y + wt.z*c.y + wt.w*e.y;
                float f2v = wt.x*a.z + wt.y*b.z + wt.z*c.z + wt.w*e.z;
                float f3v = wt.x*a.w + wt.y*b.w + wt.z*c.w + wt.w*e.w;
                sx += f0v; qx += f0v*f0v;
                sy += f1v; qy += f1v*f1v;
                sz += f2v; qz += f2v*f2v;
                sw += f3v; qw += f3v*f3v;
            }
            {
                float4 wt = s_wgt[160 + w];
                int4   ad = s_adr[160 + w];
                float4 a = __ldg(F2 + ad.x + c4);
                float4 b = __ldg(F2 + ad.y + c4);
                float4 c = __ldg(F2 + ad.z + c4);
                float4 e = __ldg(F2 + ad.w + c4);
                float f0v = wt.x*a.x + wt.y*b.x + wt.z*c.x + wt.w*e.x;
                float f1v = wt.x*a.y + wt.y*b.y + wt.z*c.y + wt.w*e.y;
                float f2v = wt.x*a.z + wt.y*b.z + wt.z*c.z + wt.w*e.z;
                float f3v = wt.x*a.w + wt.y*b.w + wt.z*c.w + wt.w*e.w;
                sx += f0v; qx += f0v*f0v;
                sy += f1v; qy += f1v*f1v;
                sz += f2v; qz += f2v*f2v;
                sw += f3v; qw += f3v*f3v;
            }

            const float inv3 = (1.0f/3.0f);
            float mx = sx*inv3, my = sy*inv3, mz = sz*inv3, mw = sw*inv3;
            float4 var = make_float4(qx*inv3 - mx*mx, qy*inv3 - my*my,
                                     qz*inv3 - mz*mz, qw*inv3 - mw*mw);
            *(float4*)(s_var + w*36 + c4*4) = var;
        }
    }
    __syncthreads();   // s_wgt/s_adr dead -> region becomes fold edges

    // zero fold-edge boundary cells (after union region is free)
    if (tid < 18) {
        int a  = tid / 9;
        int k9 = tid - a*9;
        if (a) s_e2[k9*162 + 160] = 0.0f;
        else   s_e0[k9*162 + 0]   = 0.0f;
    }

    // ---- Phase D: channel GEMM (FFMA2) + dx fold ----
    float S1[9];
    if (tid < WW) {
        int w = tid;
        ull va[16];
        const ulonglong2* qv = (const ulonglong2*)(s_var + w*36);
#pragma unroll
        for (int j = 0; j < 8; ++j) {
            ulonglong2 p = qv[j];
            va[2*j] = p.x; va[2*j+1] = p.y;
        }

#pragma unroll
        for (int k = 0; k < 27; ++k) {
            const ulonglong2* pw = (const ulonglong2*)(s_pwt + k*16);
            ull accA = 0ull, accB = 0ull;
#pragma unroll
            for (int c2 = 0; c2 < 8; ++c2) {
                ulonglong2 wp = pw[c2];
                FFMA2(accA, va[2*c2],   wp.x, accA);
                FFMA2(accB, va[2*c2+1], wp.y, accB);
            }
            float x0, x1, y0, y1;
            UNPACK2(x0, x1, accA);
            UNPACK2(y0, y1, accB);
            float S = (x0 + x1) + (y0 + y1);

            int k9 = k / 3, dx = k - k9*3;
            if (dx == 0)      s_e0[k9*162 + w + 1] = S;
            else if (dx == 1) S1[k9] = S;
            else              s_e2[k9*162 + w] = S;
        }
    }
    __syncthreads();

    if (tid < WW) {
        int w = tid;
        size_t base = (size_t)(d + 1)*SLICE + (h + 1)*ROWS + w;
#pragma unroll
        for (int k9 = 0; k9 < 9; ++k9) {
            float U = s_e0[k9*162 + w] + S1[k9] + s_e2[k9*162 + w + 1];
            g_S[(size_t)k9*CSTS + base] = U;
        }
    }
}

// ---------------------------------------------------------------------------
// Stage 3+4 fused: per-pixel 9-tap shifted-sum over all 48 depths directly
// from the U volumes (w-coalesced; repeated taps hit L1), then softmax +
// expected depth + max-prob confidence.  b_reg cancels in softmax -> ignored.
// ---------------------------------------------------------------------------
__global__ void __launch_bounds__(128)
depth_kernel(const float* __restrict__ depth_values, float* __restrict__ out)
{
    int pix = blockIdx.x * 128 + threadIdx.x;    // HW = 20480 exactly
    int h = pix / WW;
    int w = pix - h*WW;

    const float* base = g_S + h*ROWS + w;

    float cv[DD];
    float m = -1e30f;
#pragma unroll
    for (int d = 0; d < DD; ++d) {
        float acc = 0.0f;
#pragma unroll
        for (int k9 = 0; k9 < 9; ++k9) {
            int dz = k9 / 3, dy = k9 - dz*3;
            acc += __ldg(base + (size_t)k9*CSTS + (size_t)(d + dz)*SLICE + dy*ROWS);
        }
        cv[d] = acc;
        m = fmaxf(m, acc);
    }

    float sum = 0.0f, dep = 0.0f, best = 0.0f;
#pragma unroll
    for (int d = 0; d < DD; ++d) {
        float e = expf(cv[d] - m);
        sum += e;
        dep += e * __ldg(depth_values + d);
        best = fmaxf(best, e);
    }
    float isum = 1.0f / sum;
    out[pix]      = dep * isum;
    out[HW + pix] = best * isum;
}

// ---------------------------------------------------------------------------
extern "C" void kernel_launch(void* const* d_in, const int* in_sizes, int n_in,
                              void* d_out, int out_size)
{
    const float* feat0 = (const float*)d_in[0];
    const float* feat1 = (const float*)d_in[1];
    const float* feat2 = (const float*)d_in[2];
    const float* proj  = (const float*)d_in[3];
    const float* dvals = (const float*)d_in[4];
    const float* wreg  = (const float*)d_in[5];
    float* out = (float*)d_out;

    cudaFuncSetAttribute(warp_var_kernel,
                         cudaFuncAttributeMaxDynamicSharedMemorySize, SMEM_BYTES);

    prep_kernel<<<1, 1>>>(proj);
    transpose_kernel<<<dim3(HW/32, 3), dim3(32, 8)>>>(feat0, feat1, feat2);
    warp_var_kernel<<<DD*HH, 256, SMEM_BYTES>>>(dvals, wreg);
    depth_kernel<<<HW/128, 128>>>(dvals, out);
}

// round 14
// speedup vs baseline: 1.1783x; 1.0256x over previous
#include <cuda_runtime.h>
#include <cuda_bf16.h>
#include <math.h>

typedef unsigned long long ull;

// Problem constants
#define BB 1
#define CC 32
#define HH 128
#define WW 160
#define DD 48
#define HW (HH*WW)          // 20480

// Padded per-(dz,dy) partial volumes U: (9, D+2, H+2, W) — no w halo (dx folded)
#define PD (DD+2)           // 50
#define PH (HH+2)           // 130
#define ROWS   160
#define SLICE  (PH*ROWS)    // 20800
#define CSTS   (PD*SLICE)   // 1,040,000 per volume

// Device globals zero-initialized at module load; halo cells of g_S are never
// written, so SAME-padding zeros in d/h are free and persistent.
__device__ float g_rot[2][9];
__device__ float g_trans[2][3];
__device__ float g_featT[3][HW*CC];          // (view, y, x, c) channel-last
__device__ float g_S[9u*CSTS];               // 9 padded partial volumes ~37MB
__device__ float g_cost[DD*HW];              // ~3.9 MB

#define FFMA2(d, a, b, c) \
    asm("fma.rn.f32x2 %0, %1, %2, %3;" : "=l"(d) : "l"(a), "l"(b), "l"(c))
#define PACK2(out, lo, hi) \
    asm("mov.b64 %0, {%1, %2};" : "=l"(out) : "f"(lo), "f"(hi))
#define UNPACK2(lo, hi, in) \
    asm("mov.b64 {%0, %1}, %2;" : "=f"(lo), "=f"(hi) : "l"(in))

// Dynamic smem layout (bytes).  Region [0,11664) is a UNION:
//   Phase A/B: s_wgt float4[2][160] @0 (5120) | s_adr int4[2][160] @5120 (5120)
//   Phase D/E: s_e0 float[9][162] @0 (5832)   | s_e2 float[9][162] @5832 (5832)
// (wgt/adr are dead after the post-Phase-B sync; edges written after it.)
#define OFF_WGT 0
#define OFF_ADR 5120
#define OFF_E0  0
#define OFF_E2  5832
#define OFF_VAR 11664          // float [160][36]  (23040 B; w stride 144B)
#define OFF_PWT 34704          // ull [27*16]      (3456 B)
#define SMEM_BYTES 38160

// ---------------------------------------------------------------------------
// Stage 0: proj_v @ inv(proj_ref) -> rot(3x3), trans(3) for views 1,2
// ---------------------------------------------------------------------------
__global__ void prep_kernel(const float* __restrict__ proj)
{
    if (threadIdx.x != 0 || blockIdx.x != 0) return;
    float A0[9], b0[3];
    for (int r = 0; r < 3; ++r) {
        for (int c = 0; c < 3; ++c) A0[r*3+c] = proj[r*4+c];
        b0[r] = proj[r*4+3];
    }
    float inv[9];
    inv[0] =  A0[4]*A0[8] - A0[5]*A0[7];
    inv[1] = -(A0[1]*A0[8] - A0[2]*A0[7]);
    inv[2] =  A0[1]*A0[5] - A0[2]*A0[4];
    inv[3] = -(A0[3]*A0[8] - A0[5]*A0[6]);
    inv[4] =  A0[0]*A0[8] - A0[2]*A0[6];
    inv[5] = -(A0[0]*A0[5] - A0[2]*A0[3]);
    inv[6] =  A0[3]*A0[7] - A0[4]*A0[6];
    inv[7] = -(A0[0]*A0[7] - A0[1]*A0[6]);
    inv[8] =  A0[0]*A0[4] - A0[1]*A0[3];
    float det = A0[0]*inv[0] + A0[1]*inv[3] + A0[2]*inv[6];
    float idet = 1.0f / det;
    for (int i = 0; i < 9; ++i) inv[i] *= idet;

    for (int v = 1; v < 3; ++v) {
        const float* P = proj + v*16;
        float Av[9], bv[3];
        for (int r = 0; r < 3; ++r) {
            for (int c = 0; c < 3; ++c) Av[r*3+c] = P[r*4+c];
            bv[r] = P[r*4+3];
        }
        float rot[9];
        for (int r = 0; r < 3; ++r)
            for (int c = 0; c < 3; ++c)
                rot[r*3+c] = Av[r*3+0]*inv[0*3+c] + Av[r*3+1]*inv[1*3+c] + Av[r*3+2]*inv[2*3+c];
        for (int r = 0; r < 3; ++r)
            g_trans[v-1][r] = bv[r] - (rot[r*3+0]*b0[0] + rot[r*3+1]*b0[1] + rot[r*3+2]*b0[2]);
        for (int i = 0; i < 9; ++i) g_rot[v-1][i] = rot[i];
    }
}

// ---------------------------------------------------------------------------
// Stage 1: tiled transpose (C,H,W) -> (H,W,C) for all 3 views.
// ---------------------------------------------------------------------------
__global__ void transpose_kernel(const float* __restrict__ f0,
                                 const float* __restrict__ f1,
                                 const float* __restrict__ f2)
{
    __shared__ float t[32][33];
    int v  = blockIdx.y;
    int p0 = blockIdx.x * 32;
    int tx = threadIdx.x, ty = threadIdx.y;
    const float* src = (v == 0) ? f0 : (v == 1) ? f1 : f2;

#pragma unroll
    for (int j = ty; j < 32; j += 8)
        t[j][tx] = src[j*HW + p0 + tx];
    __syncthreads();
#pragma unroll
    for (int j = ty; j < 32; j += 8)
        g_featT[v][(p0 + j)*CC + tx] = t[tx][j];
}

// ---------------------------------------------------------------------------
// Stage 2: warp + variance + fused channel GEMM + dx-fold.
// Block per (d,h), 256 threads, 38.2KB smem.
//  A: bilinear weights + pixel addresses (2 views x 160 w) + packed weights.
//  B: QUAD-voxel gathers: lane = (voxel-quarter, float4 channel group); every
//     corner load is one LDG.128 serving FOUR voxels (2.25 LDG/voxel).
//  D: thread = w: 27 FFMA2 dot products over 32 channels, dx-folded into 9
//     partial values U_{dz,dy} via smem edge rows; 9 stores per voxel.
// ---------------------------------------------------------------------------
__global__ void __launch_bounds__(256)
warp_var_kernel(const float* __restrict__ depth_values,
                const float* __restrict__ w_reg)
{
    extern __shared__ char smraw[];
    float4* s_wgt = (float4*)(smraw + OFF_WGT);   // [v*160 + w]
    int4*   s_adr = (int4*)  (smraw + OFF_ADR);   // pixel*8 (float4 index)
    float*  s_var = (float*) (smraw + OFF_VAR);   // w*36 + c
    ull*    s_pwt = (ull*)   (smraw + OFF_PWT);   // k*16 + c2
    float*  s_e0  = (float*) (smraw + OFF_E0);    // k9*162 + idx
    float*  s_e2  = (float*) (smraw + OFF_E2);

    int blk = blockIdx.x;                  // 0 .. DD*HH-1
    int d = blk / HH;
    int h = blk - d*HH;
    int tid = threadIdx.x;

    float depth = __ldg(depth_values + d);

    // ---- Phase A: projection coords per (view, w) ----
    for (int t = tid; t < 2*WW; t += 256) {
        int v = t / WW;
        int w = t - v*WW;
        float fx = (float)w, fy = (float)h;

        float px = (g_rot[v][0]*fx + g_rot[v][1]*fy + g_rot[v][2]) * depth + g_trans[v][0];
        float py = (g_rot[v][3]*fx + g_rot[v][4]*fy + g_rot[v][5]) * depth + g_trans[v][1];
        float pz = (g_rot[v][6]*fx + g_rot[v][7]*fy + g_rot[v][8]) * depth + g_trans[v][2];
        float gx = px / pz;
        float gy = py / pz;

        float x0f = floorf(gx), y0f = floorf(gy);
        float wx = gx - x0f, wy = gy - y0f;
        float x1f = x0f + 1.0f, y1f = y0f + 1.0f;

        float vx0 = (x0f >= 0.0f && x0f <= (float)(WW-1)) ? 1.0f : 0.0f;
        float vx1 = (x1f >= 0.0f && x1f <= (float)(WW-1)) ? 1.0f : 0.0f;
        float vy0 = (y0f >= 0.0f && y0f <= (float)(HH-1)) ? 1.0f : 0.0f;
        float vy1 = (y1f >= 0.0f && y1f <= (float)(HH-1)) ? 1.0f : 0.0f;

        float w00 = (1.0f-wx)*(1.0f-wy) * (vx0*vy0);
        float w10 = wx*(1.0f-wy)        * (vx1*vy0);
        float w01 = (1.0f-wx)*wy        * (vx0*vy1);
        float w11 = wx*wy               * (vx1*vy1);

        int x0 = (int)fminf(fmaxf(x0f, 0.0f), (float)(WW-1));
        int x1 = (int)fminf(fmaxf(x1f, 0.0f), (float)(WW-1));
        int y0 = (int)fminf(fmaxf(y0f, 0.0f), (float)(HH-1));
        int y1 = (int)fminf(fmaxf(y1f, 0.0f), (float)(HH-1));

        s_wgt[t] = make_float4(w00, w10, w01, w11);
        s_adr[t] = make_int4((y0*WW + x0)*8, (y0*WW + x1)*8,
                             (y1*WW + x0)*8, (y1*WW + x1)*8);
    }

    // Packed weights: s_pwt[k*16+c2] = (wt[2c2][k], wt[2c2+1][k])
    for (int i = tid; i < 27*16; i += 256) {
        int k  = i >> 4;
        int c2 = i & 15;
        float lo = __ldg(w_reg + (2*c2    )*27 + k);
        float hi = __ldg(w_reg + (2*c2 + 1)*27 + k);
        ull p; PACK2(p, lo, hi);
        s_pwt[i] = p;
    }
    __syncthreads();

    // ---- Phase B: quad-voxel float4 gathers + variance ----
    {
        int lane = tid & 31;
        int warp = tid >> 5;
        int qd   = lane >> 3;          // voxel within quad (0..3)
        int c4   = lane & 7;           // float4 channel group (0..7)

        const float4* F0 = (const float4*)g_featT[0];
        const float4* F1 = (const float4*)g_featT[1];
        const float4* F2 = (const float4*)g_featT[2];

#pragma unroll
        for (int i = 0; i < 5; ++i) {
            int w = warp*20 + i*4 + qd;

            float4 ref = __ldg(F0 + (h*WW + w)*8 + c4);
            float sx = ref.x, sy = ref.y, sz = ref.z, sw = ref.w;
            float qx = ref.x*ref.x, qy = ref.y*ref.y;
            float qz = ref.z*ref.z, qw = ref.w*ref.w;

            {
                float4 wt = s_wgt[w];
                int4   ad = s_adr[w];
                float4 a = __ldg(F1 + ad.x + c4);
                float4 b = __ldg(F1 + ad.y + c4);
                float4 c = __ldg(F1 + ad.z + c4);
                float4 e = __ldg(F1 + ad.w + c4);
                float f0v = wt.x*a.x + wt.y*b.x + wt.z*c.x + wt.w*e.x;
                float f1v = wt.x*a.y + wt.y*b.y + wt.z*c.y + wt.w*e.y;
                float f2v = wt.x*a.z + wt.y*b.z + wt.z*c.z + wt.w*e.z;
                float f3v = wt.x*a.w + wt.y*b.w + wt.z*c.w + wt.w*e.w;
                sx += f0v; qx += f0v*f0v;
                sy += f1v; qy += f1v*f1v;
                sz += f2v; qz += f2v*f2v;
                sw += f3v; qw += f3v*f3v;
            }
            {
                float4 wt = s_wgt[160 + w];
                int4   ad = s_adr[160 + w];
                float4 a = __ldg(F2 + ad.x + c4);
                float4 b = __ldg(F2 + ad.y + c4);
                float4 c = __ldg(F2 + ad.z + c4);
                float4 e = __ldg(F2 + ad.w + c4);
                float f0v = wt.x*a.x + wt.y*b.x + wt.z*c.x + wt.w*e.x;
                float f1v = wt.x*a.y + wt.y*b.y + wt.z*c.y + wt.w*e.y;
                float f2v = wt.x*a.z + wt.y*b.z + wt.z*c.z + wt.w*e.z;
                float f3v = wt.x*a.w + wt.y*b.w + wt.z*c.w + wt.w*e.w;
                sx += f0v; qx += f0v*f0v;
                sy += f1v; qy += f1v*f1v;
                sz += f2v; qz += f2v*f2v;
                sw += f3v; qw += f3v*f3v;
            }

            const float inv3 = (1.0f/3.0f);
            float mx = sx*inv3, my = sy*inv3, mz = sz*inv3, mw = sw*inv3;
            float4 var = make_float4(qx*inv3 - mx*mx, qy*inv3 - my*my,
                                     qz*inv3 - mz*mz, qw*inv3 - mw*mw);
            *(float4*)(s_var + w*36 + c4*4) = var;
        }
    }
    __syncthreads();   // s_wgt/s_adr dead -> region becomes fold edges

    // zero fold-edge boundary cells (after union region is free)
    if (tid < 18) {
        int a  = tid / 9;
        int k9 = tid - a*9;
        if (a) s_e2[k9*162 + 160] = 0.0f;
        else   s_e0[k9*162 + 0]   = 0.0f;
    }

    // ---- Phase D: channel GEMM (FFMA2) + dx fold ----
    float S1[9];
    if (tid < WW) {
        int w = tid;
        ull va[16];
        const ulonglong2* qv = (const ulonglong2*)(s_var + w*36);
#pragma unroll
        for (int j = 0; j < 8; ++j) {
            ulonglong2 p = qv[j];
            va[2*j] = p.x; va[2*j+1] = p.y;
        }

#pragma unroll
        for (int k = 0; k < 27; ++k) {
            const ulonglong2* pw = (const ulonglong2*)(s_pwt + k*16);
            ull accA = 0ull, accB = 0ull;
#pragma unroll
            for (int c2 = 0; c2 < 8; ++c2) {
                ulonglong2 wp = pw[c2];
                FFMA2(accA, va[2*c2],   wp.x, accA);
                FFMA2(accB, va[2*c2+1], wp.y, accB);
            }
            float x0, x1, y0, y1;
            UNPACK2(x0, x1, accA);
            UNPACK2(y0, y1, accB);
            float S = (x0 + x1) + (y0 + y1);

            int k9 = k / 3, dx = k - k9*3;
            if (dx == 0)      s_e0[k9*162 + w + 1] = S;
            else if (dx == 1) S1[k9] = S;
            else              s_e2[k9*162 + w] = S;
        }
    }
    __syncthreads();

    if (tid < WW) {
        int w = tid;
        size_t base = (size_t)(d + 1)*SLICE + (h + 1)*ROWS + w;
#pragma unroll
        for (int k9 = 0; k9 < 9; ++k9) {
            float U = s_e0[k9*162 + w] + S1[k9] + s_e2[k9*162 + w + 1];
            g_S[(size_t)k9*CSTS + base] = U;
        }
    }
}

// ---------------------------------------------------------------------------
// Stage 3: 9-tap shifted-sum of partial volumes -> cost, 2x float4 per thread
// for deeper MLP (18 independent loads in flight).
// ---------------------------------------------------------------------------
__global__ void __launch_bounds__(256)
sum_kernel()
{
    int idx = blockIdx.x * 256 + threadIdx.x;      // DD*HH*WW/8 = 122880
    int w8 = idx % 20;                             // 20 8-wide groups per row
    int t  = idx / 20;
    int h  = t % HH;
    int d  = t / HH;

    const float* base = g_S + (size_t)d*SLICE + h*ROWS + w8*8;
    float ax = 0.0f, ay = 0.0f, az = 0.0f, aw = 0.0f;
    float bx = 0.0f, by = 0.0f, bz = 0.0f, bw = 0.0f;
#pragma unroll
    for (int k9 = 0; k9 < 9; ++k9) {
        int dz = k9 / 3, dy = k9 - dz*3;
        const float* p = base + (size_t)k9*CSTS + dz*SLICE + dy*ROWS;
        float4 v0 = *(const float4*)p;
        float4 v1 = *(const float4*)(p + 4);
        ax += v0.x; ay += v0.y; az += v0.z; aw += v0.w;
        bx += v1.x; by += v1.y; bz += v1.z; bw += v1.w;
    }
    float* op = g_cost + d*HW + h*WW + w8*8;
    *(float4*)op       = make_float4(ax, ay, az, aw);
    *(float4*)(op + 4) = make_float4(bx, by, bz, bw);
}

// ---------------------------------------------------------------------------
// Stage 4: softmax over D, expected depth + max-prob confidence.
// 64-thread blocks (grid 320) for >=2 blocks/SM of latency hiding.
// b_reg shifts all logits equally -> cancels in softmax -> ignored.
// ---------------------------------------------------------------------------
__global__ void __launch_bounds__(64)
depth_kernel(const float* __restrict__ depth_values, float* __restrict__ out)
{
    int pix = blockIdx.x * 64 + threadIdx.x;     // HW = 20480 exactly
    float cv[DD];
    float m = -1e30f;
#pragma unroll
    for (int d = 0; d < DD; ++d) {
        cv[d] = g_cost[d*HW + pix];
        m = fmaxf(m, cv[d]);
    }
    float sum = 0.0f, dep = 0.0f, best = 0.0f;
#pragma unroll
    for (int d = 0; d < DD; ++d) {
        float e = expf(cv[d] - m);
        sum += e;
        dep += e * __ldg(depth_values + d);
        best = fmaxf(best, e);
    }
    float isum = 1.0f / sum;
    out[pix]      = dep * isum;
    out[HW + pix] = best * isum;
}

// ---------------------------------------------------------------------------
extern "C" void kernel_launch(void* const* d_in, const int* in_sizes, int n_in,
                              void* d_out, int out_size)
{
    const float* feat0 = (const float*)d_in[0];
    const float* feat1 = (const float*)d_in[1];
    const float* feat2 = (const float*)d_in[2];
    const float* proj  = (const float*)d_in[3];
    const float* dvals = (const float*)d_in[4];
    const float* wreg  = (const float*)d_in[5];
    float* out = (float*)d_out;

    cudaFuncSetAttribute(warp_var_kernel,
                         cudaFuncAttributeMaxDynamicSharedMemorySize, SMEM_BYTES);

    prep_kernel<<<1, 1>>>(proj);
    transpose_kernel<<<dim3(HW/32, 3), dim3(32, 8)>>>(feat0, feat1, feat2);
    warp_var_kernel<<<DD*HH, 256, SMEM_BYTES>>>(dvals, wreg);
    sum_kernel<<<(DD*HH*WW/8)/256, 256>>>();
    depth_kernel<<<HW/64, 64>>>(dvals, out);
}

// round 15
// speedup vs baseline: 1.2113x; 1.0280x over previous
#include <cuda_runtime.h>
#include <cuda_bf16.h>
#include <cuda_fp16.h>
#include <math.h>

typedef unsigned long long ull;

// Problem constants
#define BB 1
#define CC 32
#define HH 128
#define WW 160
#define DD 48
#define HW (HH*WW)          // 20480

// Padded per-(dz,dy) partial volumes U: (9, D+2, H+2, W) — no w halo (dx folded)
#define PD (DD+2)           // 50
#define PH (HH+2)           // 130
#define ROWS   160
#define SLICE  (PH*ROWS)    // 20800
#define CSTS   (PD*SLICE)   // 1,040,000 per volume

// Device globals zero-initialized at module load; halo cells of g_S are never
// written, so SAME-padding zeros in d/h are free and persistent.
__device__ float g_rot[2][9];
__device__ float g_trans[2][3];
__device__ __half g_featTh[3][HW*CC];        // (view, y, x, c) channel-last fp16
__device__ float g_S[9u*CSTS];               // 9 padded partial volumes ~37MB
__device__ float g_cost[DD*HW];              // ~3.9 MB

#define FFMA2(d, a, b, c) \
    asm("fma.rn.f32x2 %0, %1, %2, %3;" : "=l"(d) : "l"(a), "l"(b), "l"(c))
#define PACK2(out, lo, hi) \
    asm("mov.b64 %0, {%1, %2};" : "=l"(out) : "f"(lo), "f"(hi))
#define UNPACK2(lo, hi, in) \
    asm("mov.b64 {%0, %1}, %2;" : "=f"(lo), "=f"(hi) : "l"(in))

// Dynamic smem layout (bytes).  Region [0,11664) is a UNION:
//   Phase A/B: s_wgt float4[2][160] @0 (5120) | s_adr int4[2][160] @5120 (5120)
//   Phase D/E: s_e0 float[9][162] @0 (5832)   | s_e2 float[9][162] @5832 (5832)
#define OFF_WGT 0
#define OFF_ADR 5120
#define OFF_E0  0
#define OFF_E2  5832
#define OFF_VAR 11664          // float [160][36]  (23040 B; w stride 144B)
#define OFF_PWT 34704          // ull [27*16]      (3456 B)
#define SMEM_BYTES 38160

// Convert 8 packed halves (uint4) to 8 floats
__device__ __forceinline__ void H8F(uint4 u, float* f)
{
    float2 t0 = __half22float2(*(__half2*)&u.x);
    float2 t1 = __half22float2(*(__half2*)&u.y);
    float2 t2 = __half22float2(*(__half2*)&u.z);
    float2 t3 = __half22float2(*(__half2*)&u.w);
    f[0]=t0.x; f[1]=t0.y; f[2]=t1.x; f[3]=t1.y;
    f[4]=t2.x; f[5]=t2.y; f[6]=t3.x; f[7]=t3.y;
}

// ---------------------------------------------------------------------------
// Stage 0: proj_v @ inv(proj_ref) -> rot(3x3), trans(3) for views 1,2
// ---------------------------------------------------------------------------
__global__ void prep_kernel(const float* __restrict__ proj)
{
    if (threadIdx.x != 0 || blockIdx.x != 0) return;
    float A0[9], b0[3];
    for (int r = 0; r < 3; ++r) {
        for (int c = 0; c < 3; ++c) A0[r*3+c] = proj[r*4+c];
        b0[r] = proj[r*4+3];
    }
    float inv[9];
    inv[0] =  A0[4]*A0[8] - A0[5]*A0[7];
    inv[1] = -(A0[1]*A0[8] - A0[2]*A0[7]);
    inv[2] =  A0[1]*A0[5] - A0[2]*A0[4];
    inv[3] = -(A0[3]*A0[8] - A0[5]*A0[6]);
    inv[4] =  A0[0]*A0[8] - A0[2]*A0[6];
    inv[5] = -(A0[0]*A0[5] - A0[2]*A0[3]);
    inv[6] =  A0[3]*A0[7] - A0[4]*A0[6];
    inv[7] = -(A0[0]*A0[7] - A0[1]*A0[6]);
    inv[8] =  A0[0]*A0[4] - A0[1]*A0[3];
    float det = A0[0]*inv[0] + A0[1]*inv[3] + A0[2]*inv[6];
    float idet = 1.0f / det;
    for (int i = 0; i < 9; ++i) inv[i] *= idet;

    for (int v = 1; v < 3; ++v) {
        const float* P = proj + v*16;
        float Av[9], bv[3];
        for (int r = 0; r < 3; ++r) {
            for (int c = 0; c < 3; ++c) Av[r*3+c] = P[r*4+c];
            bv[r] = P[r*4+3];
        }
        float rot[9];
        for (int r = 0; r < 3; ++r)
            for (int c = 0; c < 3; ++c)
                rot[r*3+c] = Av[r*3+0]*inv[0*3+c] + Av[r*3+1]*inv[1*3+c] + Av[r*3+2]*inv[2*3+c];
        for (int r = 0; r < 3; ++r)
            g_trans[v-1][r] = bv[r] - (rot[r*3+0]*b0[0] + rot[r*3+1]*b0[1] + rot[r*3+2]*b0[2]);
        for (int i = 0; i < 9; ++i) g_rot[v-1][i] = rot[i];
    }
}

// ---------------------------------------------------------------------------
// Stage 1: tiled transpose (C,H,W) -> (H,W,C) fp32 -> fp16 for all 3 views.
// ---------------------------------------------------------------------------
__global__ void transpose_kernel(const float* __restrict__ f0,
                                 const float* __restrict__ f1,
                                 const float* __restrict__ f2)
{
    __shared__ float t[32][33];
    int v  = blockIdx.y;
    int p0 = blockIdx.x * 32;
    int tx = threadIdx.x, ty = threadIdx.y;
    const float* src = (v == 0) ? f0 : (v == 1) ? f1 : f2;

#pragma unroll
    for (int j = ty; j < 32; j += 8)
        t[j][tx] = src[j*HW + p0 + tx];
    __syncthreads();
#pragma unroll
    for (int j = ty; j < 32; j += 8)
        g_featTh[v][(p0 + j)*CC + tx] = __float2half(t[tx][j]);
}

// ---------------------------------------------------------------------------
// Stage 2: warp + variance + fused channel GEMM + dx-fold (fp16 features).
// Block per (d,h), 256 threads, 38.2KB smem.
//  B: OCTET-voxel gathers: lane = (voxel qd 0..7, half8-group c4 0..3);
//     every corner load is one LDG.128 of 8 fp16 channels serving EIGHT
//     voxels per warp instruction (1.125 LDG/voxel, 576 B/voxel through L2).
//     All arithmetic fp32 after __half22float2.
//  D: thread = w: 27 FFMA2 dot products over 32 channels, dx-folded into 9
//     partial values U_{dz,dy} via smem edge rows; 9 stores per voxel.
// ---------------------------------------------------------------------------
__global__ void __launch_bounds__(256)
warp_var_kernel(const float* __restrict__ depth_values,
                const float* __restrict__ w_reg)
{
    extern __shared__ char smraw[];
    float4* s_wgt = (float4*)(smraw + OFF_WGT);   // [v*160 + w]
    int4*   s_adr = (int4*)  (smraw + OFF_ADR);   // pixel*4 (uint4 index)
    float*  s_var = (float*) (smraw + OFF_VAR);   // w*36 + c
    ull*    s_pwt = (ull*)   (smraw + OFF_PWT);   // k*16 + c2
    float*  s_e0  = (float*) (smraw + OFF_E0);    // k9*162 + idx
    float*  s_e2  = (float*) (smraw + OFF_E2);

    int blk = blockIdx.x;                  // 0 .. DD*HH-1
    int d = blk / HH;
    int h = blk - d*HH;
    int tid = threadIdx.x;

    float depth = __ldg(depth_values + d);

    // ---- Phase A: projection coords per (view, w) ----
    for (int t = tid; t < 2*WW; t += 256) {
        int v = t / WW;
        int w = t - v*WW;
        float fx = (float)w, fy = (float)h;

        float px = (g_rot[v][0]*fx + g_rot[v][1]*fy + g_rot[v][2]) * depth + g_trans[v][0];
        float py = (g_rot[v][3]*fx + g_rot[v][4]*fy + g_rot[v][5]) * depth + g_trans[v][1];
        float pz = (g_rot[v][6]*fx + g_rot[v][7]*fy + g_rot[v][8]) * depth + g_trans[v][2];
        float gx = px / pz;
        float gy = py / pz;

        float x0f = floorf(gx), y0f = floorf(gy);
        float wx = gx - x0f, wy = gy - y0f;
        float x1f = x0f + 1.0f, y1f = y0f + 1.0f;

        float vx0 = (x0f >= 0.0f && x0f <= (float)(WW-1)) ? 1.0f : 0.0f;
        float vx1 = (x1f >= 0.0f && x1f <= (float)(WW-1)) ? 1.0f : 0.0f;
        float vy0 = (y0f >= 0.0f && y0f <= (float)(HH-1)) ? 1.0f : 0.0f;
        float vy1 = (y1f >= 0.0f && y1f <= (float)(HH-1)) ? 1.0f : 0.0f;

        float w00 = (1.0f-wx)*(1.0f-wy) * (vx0*vy0);
        float w10 = wx*(1.0f-wy)        * (vx1*vy0);
        float w01 = (1.0f-wx)*wy        * (vx0*vy1);
        float w11 = wx*wy               * (vx1*vy1);

        int x0 = (int)fminf(fmaxf(x0f, 0.0f), (float)(WW-1));
        int x1 = (int)fminf(fmaxf(x1f, 0.0f), (float)(WW-1));
        int y0 = (int)fminf(fmaxf(y0f, 0.0f), (float)(HH-1));
        int y1 = (int)fminf(fmaxf(y1f, 0.0f), (float)(HH-1));

        s_wgt[t] = make_float4(w00, w10, w01, w11);
        s_adr[t] = make_int4((y0*WW + x0)*4, (y0*WW + x1)*4,
                             (y1*WW + x0)*4, (y1*WW + x1)*4);
    }

    // Packed weights: s_pwt[k*16+c2] = (wt[2c2][k], wt[2c2+1][k])
    for (int i = tid; i < 27*16; i += 256) {
        int k  = i >> 4;
        int c2 = i & 15;
        float lo = __ldg(w_reg + (2*c2    )*27 + k);
        float hi = __ldg(w_reg + (2*c2 + 1)*27 + k);
        ull p; PACK2(p, lo, hi);
        s_pwt[i] = p;
    }
    __syncthreads();

    // ---- Phase B: octet-voxel fp16 gathers + fp32 variance ----
    {
        int lane = tid & 31;
        int warp = tid >> 5;
        int qd   = lane >> 2;          // voxel within octet (0..7)
        int c4   = lane & 3;           // half8 channel group (0..3)

        const uint4* F0 = (const uint4*)g_featTh[0];
        const uint4* F1 = (const uint4*)g_featTh[1];
        const uint4* F2 = (const uint4*)g_featTh[2];

#pragma unroll
        for (int i = 0; i < 3; ++i) {
            if (i == 2 && qd >= 4) break;       // 20 voxels per warp
            int w = warp*20 + i*8 + qd;

            float s[8], q[8];
            {
                uint4 r = __ldg(F0 + (h*WW + w)*4 + c4);
                float f[8]; H8F(r, f);
#pragma unroll
                for (int j = 0; j < 8; ++j) { s[j] = f[j]; q[j] = f[j]*f[j]; }
            }

#pragma unroll
            for (int v = 0; v < 2; ++v) {
                const uint4* Fv = v ? F2 : F1;
                float4 wt = s_wgt[v*160 + w];
                int4   ad = s_adr[v*160 + w];
                uint4 A = __ldg(Fv + ad.x + c4);
                uint4 B = __ldg(Fv + ad.y + c4);
                uint4 C = __ldg(Fv + ad.z + c4);
                uint4 E = __ldg(Fv + ad.w + c4);

                float acc[8];
                {
                    float f[8]; H8F(A, f);
#pragma unroll
                    for (int j = 0; j < 8; ++j) acc[j] = wt.x*f[j];
                }
                {
                    float f[8]; H8F(B, f);
#pragma unroll
                    for (int j = 0; j < 8; ++j) acc[j] = fmaf(wt.y, f[j], acc[j]);
                }
                {
                    float f[8]; H8F(C, f);
#pragma unroll
                    for (int j = 0; j < 8; ++j) acc[j] = fmaf(wt.z, f[j], acc[j]);
                }
                {
                    float f[8]; H8F(E, f);
#pragma unroll
                    for (int j = 0; j < 8; ++j) acc[j] = fmaf(wt.w, f[j], acc[j]);
                }
#pragma unroll
                for (int j = 0; j < 8; ++j) {
                    s[j] += acc[j];
                    q[j] = fmaf(acc[j], acc[j], q[j]);
                }
            }

            const float inv3 = (1.0f/3.0f);
            float o[8];
#pragma unroll
            for (int j = 0; j < 8; ++j) {
                float m = s[j] * inv3;
                o[j] = q[j]*inv3 - m*m;
            }
            *(float4*)(s_var + w*36 + c4*8)     = make_float4(o[0], o[1], o[2], o[3]);
            *(float4*)(s_var + w*36 + c4*8 + 4) = make_float4(o[4], o[5], o[6], o[7]);
        }
    }
    __syncthreads();   // s_wgt/s_adr dead -> region becomes fold edges

    // zero fold-edge boundary cells (after union region is free)
    if (tid < 18) {
        int a  = tid / 9;
        int k9 = tid - a*9;
        if (a) s_e2[k9*162 + 160] = 0.0f;
        else   s_e0[k9*162 + 0]   = 0.0f;
    }

    // ---- Phase D: channel GEMM (FFMA2) + dx fold ----
    float S1[9];
    if (tid < WW) {
        int w = tid;
        ull va[16];
        const ulonglong2* qv = (const ulonglong2*)(s_var + w*36);
#pragma unroll
        for (int j = 0; j < 8; ++j) {
            ulonglong2 p = qv[j];
            va[2*j] = p.x; va[2*j+1] = p.y;
        }

#pragma unroll
        for (int k = 0; k < 27; ++k) {
            const ulonglong2* pw = (const ulonglong2*)(s_pwt + k*16);
            ull accA = 0ull, accB = 0ull;
#pragma unroll
            for (int c2 = 0; c2 < 8; ++c2) {
                ulonglong2 wp = pw[c2];
                FFMA2(accA, va[2*c2],   wp.x, accA);
                FFMA2(accB, va[2*c2+1], wp.y, accB);
            }
            float x0, x1, y0, y1;
            UNPACK2(x0, x1, accA);
            UNPACK2(y0, y1, accB);
            float S = (x0 + x1) + (y0 + y1);

            int k9 = k / 3, dx = k - k9*3;
            if (dx == 0)      s_e0[k9*162 + w + 1] = S;
            else if (dx == 1) S1[k9] = S;
            else              s_e2[k9*162 + w] = S;
        }
    }
    __syncthreads();

    if (tid < WW) {
        int w = tid;
        size_t base = (size_t)(d + 1)*SLICE + (h + 1)*ROWS + w;
#pragma unroll
        for (int k9 = 0; k9 < 9; ++k9) {
            float U = s_e0[k9*162 + w] + S1[k9] + s_e2[k9*162 + w + 1];
            g_S[(size_t)k9*CSTS + base] = U;
        }
    }
}

// ---------------------------------------------------------------------------
// Stage 3: 9-tap shifted-sum of partial volumes -> cost, 2x float4 per thread.
// ---------------------------------------------------------------------------
__global__ void __launch_bounds__(256)
sum_kernel()
{
    int idx = blockIdx.x * 256 + threadIdx.x;      // DD*HH*WW/8 = 122880
    int w8 = idx % 20;
    int t  = idx / 20;
    int h  = t % HH;
    int d  = t / HH;

    const float* base = g_S + (size_t)d*SLICE + h*ROWS + w8*8;
    float ax = 0.0f, ay = 0.0f, az = 0.0f, aw = 0.0f;
    float bx = 0.0f, by = 0.0f, bz = 0.0f, bw = 0.0f;
#pragma unroll
    for (int k9 = 0; k9 < 9; ++k9) {
        int dz = k9 / 3, dy = k9 - dz*3;
        const float* p = base + (size_t)k9*CSTS + dz*SLICE + dy*ROWS;
        float4 v0 = *(const float4*)p;
        float4 v1 = *(const float4*)(p + 4);
        ax += v0.x; ay += v0.y; az += v0.z; aw += v0.w;
        bx += v1.x; by += v1.y; bz += v1.z; bw += v1.w;
    }
    float* op = g_cost + d*HW + h*WW + w8*8;
    *(float4*)op       = make_float4(ax, ay, az, aw);
    *(float4*)(op + 4) = make_float4(bx, by, bz, bw);
}

// ---------------------------------------------------------------------------
// Stage 4: softmax over D, expected depth + max-prob confidence.
// ---------------------------------------------------------------------------
__global__ void __launch_bounds__(64)
depth_kernel(const float* __restrict__ depth_values, float* __restrict__ out)
{
    int pix = blockIdx.x * 64 + threadIdx.x;     // HW = 20480 exactly
    float cv[DD];
    float m = -1e30f;
#pragma unroll
    for (int d = 0; d < DD; ++d) {
        cv[d] = g_cost[d*HW + pix];
        m = fmaxf(m, cv[d]);
    }
    float sum = 0.0f, dep = 0.0f, best = 0.0f;
#pragma unroll
    for (int d = 0; d < DD; ++d) {
        float e = expf(cv[d] - m);
        sum += e;
        dep += e * __ldg(depth_values + d);
        best = fmaxf(best, e);
    }
    float isum = 1.0f / sum;
    out[pix]      = dep * isum;
    out[HW + pix] = best * isum;
}

// ---------------------------------------------------------------------------
extern "C" void kernel_launch(void* const* d_in, const int* in_sizes, int n_in,
                              void* d_out, int out_size)
{
    const float* feat0 = (const float*)d_in[0];
    const float* feat1 = (const float*)d_in[1];
    const float* feat2 = (const float*)d_in[2];
    const float* proj  = (const float*)d_in[3];
    const float* dvals = (const float*)d_in[4];
    const float* wreg  = (const float*)d_in[5];
    float* out = (float*)d_out;

    cudaFuncSetAttribute(warp_var_kernel,
                         cudaFuncAttributeMaxDynamicSharedMemorySize, SMEM_BYTES);

    prep_kernel<<<1, 1>>>(proj);
    transpose_kernel<<<dim3(HW/32, 3), dim3(32, 8)>>>(feat0, feat1, feat2);
    warp_var_kernel<<<DD*HH, 256, SMEM_BYTES>>>(dvals, wreg);
    sum_kernel<<<(DD*HH*WW/8)/256, 256>>>();
    depth_kernel<<<HW/64, 64>>>(dvals, out);
}

// round 16
// speedup vs baseline: 1.3199x; 1.0897x over previous
#include <cuda_runtime.h>
#include <cuda_bf16.h>
#include <cuda_fp16.h>
#include <math.h>

typedef unsigned long long ull;

// Problem constants
#define BB 1
#define CC 32
#define HH 128
#define WW 160
#define DD 48
#define HW (HH*WW)          // 20480

// Padded per-(dz,dy) partial volumes U: (9, D+2, H+2, W) — no w halo (dx folded)
#define PD (DD+2)           // 50
#define PH (HH+2)           // 130
#define ROWS   160
#define SLICE  (PH*ROWS)    // 20800
#define CSTS   (PD*SLICE)   // 1,040,000 per volume

// Device globals zero-initialized at module load; halo cells of g_S are never
// written, so SAME-padding zeros in d/h are free and persistent.
__device__ float g_rot[2][9];
__device__ float g_trans[2][3];
__device__ __half g_featTh[3][HW*CC];        // (view, y, x, c) channel-last fp16
__device__ float g_S[9u*CSTS];               // 9 padded partial volumes ~37MB
__device__ float g_cost[DD*HW];              // ~3.9 MB

#define FFMA2(d, a, b, c) \
    asm("fma.rn.f32x2 %0, %1, %2, %3;" : "=l"(d) : "l"(a), "l"(b), "l"(c))
#define PACK2(out, lo, hi) \
    asm("mov.b64 %0, {%1, %2};" : "=l"(out) : "f"(lo), "f"(hi))
#define UNPACK2(lo, hi, in) \
    asm("mov.b64 {%0, %1}, %2;" : "=f"(lo), "=f"(hi) : "l"(in))

// Dynamic smem layout (bytes).  Region [0,11664) is a UNION:
//   Phase A/B: s_hwt uint4[2][160] @0 (5120) | s_adr int4[2][160] @5120 (5120)
//   Phase D/E: s_e0 float[9][162] @0 (5832)  | s_e2 float[9][162] @5832 (5832)
#define OFF_HWT 0
#define OFF_ADR 5120
#define OFF_E0  0
#define OFF_E2  5832
#define OFF_VAR 11664          // float [160][36]  (23040 B; w stride 144B)
#define OFF_PWT 34704          // ull [27*16]      (3456 B)
#define SMEM_BYTES 38160

// Convert 8 packed halves (uint4) to 8 floats
__device__ __forceinline__ void H8F(uint4 u, float* f)
{
    float2 t0 = __half22float2(*(__half2*)&u.x);
    float2 t1 = __half22float2(*(__half2*)&u.y);
    float2 t2 = __half22float2(*(__half2*)&u.z);
    float2 t3 = __half22float2(*(__half2*)&u.w);
    f[0]=t0.x; f[1]=t0.y; f[2]=t1.x; f[3]=t1.y;
    f[4]=t2.x; f[5]=t2.y; f[6]=t3.x; f[7]=t3.y;
}

// ---------------------------------------------------------------------------
// Stage 0: proj_v @ inv(proj_ref) -> rot(3x3), trans(3) for views 1,2
// ---------------------------------------------------------------------------
__global__ void prep_kernel(const float* __restrict__ proj)
{
    if (threadIdx.x != 0 || blockIdx.x != 0) return;
    float A0[9], b0[3];
    for (int r = 0; r < 3; ++r) {
        for (int c = 0; c < 3; ++c) A0[r*3+c] = proj[r*4+c];
        b0[r] = proj[r*4+3];
    }
    float inv[9];
    inv[0] =  A0[4]*A0[8] - A0[5]*A0[7];
    inv[1] = -(A0[1]*A0[8] - A0[2]*A0[7]);
    inv[2] =  A0[1]*A0[5] - A0[2]*A0[4];
    inv[3] = -(A0[3]*A0[8] - A0[5]*A0[6]);
    inv[4] =  A0[0]*A0[8] - A0[2]*A0[6];
    inv[5] = -(A0[0]*A0[5] - A0[2]*A0[3]);
    inv[6] =  A0[3]*A0[7] - A0[4]*A0[6];
    inv[7] = -(A0[0]*A0[7] - A0[1]*A0[6]);
    inv[8] =  A0[0]*A0[4] - A0[1]*A0[3];
    float det = A0[0]*inv[0] + A0[1]*inv[3] + A0[2]*inv[6];
    float idet = 1.0f / det;
    for (int i = 0; i < 9; ++i) inv[i] *= idet;

    for (int v = 1; v < 3; ++v) {
        const float* P = proj + v*16;
        float Av[9], bv[3];
        for (int r = 0; r < 3; ++r) {
            for (int c = 0; c < 3; ++c) Av[r*3+c] = P[r*4+c];
            bv[r] = P[r*4+3];
        }
        float rot[9];
        for (int r = 0; r < 3; ++r)
            for (int c = 0; c < 3; ++c)
                rot[r*3+c] = Av[r*3+0]*inv[0*3+c] + Av[r*3+1]*inv[1*3+c] + Av[r*3+2]*inv[2*3+c];
        for (int r = 0; r < 3; ++r)
            g_trans[v-1][r] = bv[r] - (rot[r*3+0]*b0[0] + rot[r*3+1]*b0[1] + rot[r*3+2]*b0[2]);
        for (int i = 0; i < 9; ++i) g_rot[v-1][i] = rot[i];
    }
}

// ---------------------------------------------------------------------------
// Stage 1: tiled transpose (C,H,W) -> (H,W,C) fp32 -> fp16 for all 3 views.
// ---------------------------------------------------------------------------
__global__ void transpose_kernel(const float* __restrict__ f0,
                                 const float* __restrict__ f1,
                                 const float* __restrict__ f2)
{
    __shared__ float t[32][33];
    int v  = blockIdx.y;
    int p0 = blockIdx.x * 32;
    int tx = threadIdx.x, ty = threadIdx.y;
    const float* src = (v == 0) ? f0 : (v == 1) ? f1 : f2;

#pragma unroll
    for (int j = ty; j < 32; j += 8)
        t[j][tx] = src[j*HW + p0 + tx];
    __syncthreads();
#pragma unroll
    for (int j = ty; j < 32; j += 8)
        g_featTh[v][(p0 + j)*CC + tx] = __float2half(t[tx][j]);
}

// ---------------------------------------------------------------------------
// Stage 2: warp + variance + fused channel GEMM + dx-fold (fp16 features).
// Block per (d,h), 256 threads, 38.2KB smem.
//  B: OCTET-voxel gathers (LDG.128 of 8 fp16 channels serves 8 voxels);
//     4-corner bilinear blend in NATIVE half2 (HFMA2, weights as duplicated
//     half2), only the blended result converted to fp32; variance fp32.
//  D: thread = w: 27 FFMA2 dot products over 32 channels, dx-folded into 9
//     partial values U_{dz,dy} via smem edge rows; 9 stores per voxel.
// ---------------------------------------------------------------------------
__global__ void __launch_bounds__(256)
warp_var_kernel(const float* __restrict__ depth_values,
                const float* __restrict__ w_reg)
{
    extern __shared__ char smraw[];
    uint4*  s_hwt = (uint4*) (smraw + OFF_HWT);   // [v*160+w]: 4 dup'd half2
    int4*   s_adr = (int4*)  (smraw + OFF_ADR);   // pixel*4 (uint4 index)
    float*  s_var = (float*) (smraw + OFF_VAR);   // w*36 + c
    ull*    s_pwt = (ull*)   (smraw + OFF_PWT);   // k*16 + c2
    float*  s_e0  = (float*) (smraw + OFF_E0);    // k9*162 + idx
    float*  s_e2  = (float*) (smraw + OFF_E2);

    int blk = blockIdx.x;                  // 0 .. DD*HH-1
    int d = blk / HH;
    int h = blk - d*HH;
    int tid = threadIdx.x;

    float depth = __ldg(depth_values + d);

    // ---- Phase A: projection coords per (view, w) ----
    for (int t = tid; t < 2*WW; t += 256) {
        int v = t / WW;
        int w = t - v*WW;
        float fx = (float)w, fy = (float)h;

        float px = (g_rot[v][0]*fx + g_rot[v][1]*fy + g_rot[v][2]) * depth + g_trans[v][0];
        float py = (g_rot[v][3]*fx + g_rot[v][4]*fy + g_rot[v][5]) * depth + g_trans[v][1];
        float pz = (g_rot[v][6]*fx + g_rot[v][7]*fy + g_rot[v][8]) * depth + g_trans[v][2];
        float gx = __fdividef(px, pz);
        float gy = __fdividef(py, pz);

        float x0f = floorf(gx), y0f = floorf(gy);
        float wx = gx - x0f, wy = gy - y0f;
        float x1f = x0f + 1.0f, y1f = y0f + 1.0f;

        float vx0 = (x0f >= 0.0f && x0f <= (float)(WW-1)) ? 1.0f : 0.0f;
        float vx1 = (x1f >= 0.0f && x1f <= (float)(WW-1)) ? 1.0f : 0.0f;
        float vy0 = (y0f >= 0.0f && y0f <= (float)(HH-1)) ? 1.0f : 0.0f;
        float vy1 = (y1f >= 0.0f && y1f <= (float)(HH-1)) ? 1.0f : 0.0f;

        float w00 = (1.0f-wx)*(1.0f-wy) * (vx0*vy0);
        float w10 = wx*(1.0f-wy)        * (vx1*vy0);
        float w01 = (1.0f-wx)*wy        * (vx0*vy1);
        float w11 = wx*wy               * (vx1*vy1);

        int x0 = (int)fminf(fmaxf(x0f, 0.0f), (float)(WW-1));
        int x1 = (int)fminf(fmaxf(x1f, 0.0f), (float)(WW-1));
        int y0 = (int)fminf(fmaxf(y0f, 0.0f), (float)(HH-1));
        int y1 = (int)fminf(fmaxf(y1f, 0.0f), (float)(HH-1));

        // duplicated-half2 weights for HFMA2 blending
        __half2 h00 = __float2half2_rn(w00);
        __half2 h10 = __float2half2_rn(w10);
        __half2 h01 = __float2half2_rn(w01);
        __half2 h11 = __float2half2_rn(w11);
        uint4 hw;
        hw.x = *(unsigned*)&h00;
        hw.y = *(unsigned*)&h10;
        hw.z = *(unsigned*)&h01;
        hw.w = *(unsigned*)&h11;
        s_hwt[t] = hw;
        s_adr[t] = make_int4((y0*WW + x0)*4, (y0*WW + x1)*4,
                             (y1*WW + x0)*4, (y1*WW + x1)*4);
    }

    // Packed fp32 weights: s_pwt[k*16+c2] = (wt[2c2][k], wt[2c2+1][k])
    for (int i = tid; i < 27*16; i += 256) {
        int k  = i >> 4;
        int c2 = i & 15;
        float lo = __ldg(w_reg + (2*c2    )*27 + k);
        float hi = __ldg(w_reg + (2*c2 + 1)*27 + k);
        ull p; PACK2(p, lo, hi);
        s_pwt[i] = p;
    }
    __syncthreads();

    // ---- Phase B: octet-voxel fp16 gathers + HFMA2 blend + fp32 variance ----
    {
        int lane = tid & 31;
        int warp = tid >> 5;
        int qd   = lane >> 2;          // voxel within octet (0..7)
        int c4   = lane & 3;           // half8 channel group (0..3)

        const uint4* F0 = (const uint4*)g_featTh[0];
        const uint4* F1 = (const uint4*)g_featTh[1];
        const uint4* F2 = (const uint4*)g_featTh[2];

#pragma unroll
        for (int i = 0; i < 3; ++i) {
            if (i == 2 && qd >= 4) break;       // 20 voxels per warp
            int w = warp*20 + i*8 + qd;

            float s[8], q[8];
            {
                uint4 r = __ldg(F0 + (h*WW + w)*4 + c4);
                float f[8]; H8F(r, f);
#pragma unroll
                for (int j = 0; j < 8; ++j) { s[j] = f[j]; q[j] = f[j]*f[j]; }
            }

#pragma unroll
            for (int v = 0; v < 2; ++v) {
                const uint4* Fv = v ? F2 : F1;
                uint4 hw = s_hwt[v*160 + w];
                __half2 w00 = *(__half2*)&hw.x;
                __half2 w10 = *(__half2*)&hw.y;
                __half2 w01 = *(__half2*)&hw.z;
                __half2 w11 = *(__half2*)&hw.w;
                int4  ad = s_adr[v*160 + w];
                uint4 A = __ldg(Fv + ad.x + c4);
                uint4 B = __ldg(Fv + ad.y + c4);
                uint4 C = __ldg(Fv + ad.z + c4);
                uint4 E = __ldg(Fv + ad.w + c4);

                // 4-corner blend in half2 (2 channels per op)
                uint4 R;
                {
                    __half2 a = *(__half2*)&A.x, b = *(__half2*)&B.x;
                    __half2 c = *(__half2*)&C.x, e = *(__half2*)&E.x;
                    __half2 f = __hfma2(w10, b, __hmul2(w00, a));
                    f = __hfma2(w01, c, f);
                    f = __hfma2(w11, e, f);
                    R.x = *(unsigned*)&f;
                }
                {
                    __half2 a = *(__half2*)&A.y, b = *(__half2*)&B.y;
                    __half2 c = *(__half2*)&C.y, e = *(__half2*)&E.y;
                    __half2 f = __hfma2(w10, b, __hmul2(w00, a));
                    f = __hfma2(w01, c, f);
                    f = __hfma2(w11, e, f);
                    R.y = *(unsigned*)&f;
                }
                {
                    __half2 a = *(__half2*)&A.z, b = *(__half2*)&B.z;
                    __half2 c = *(__half2*)&C.z, e = *(__half2*)&E.z;
                    __half2 f = __hfma2(w10, b, __hmul2(w00, a));
                    f = __hfma2(w01, c, f);
                    f = __hfma2(w11, e, f);
                    R.z = *(unsigned*)&f;
                }
                {
                    __half2 a = *(__half2*)&A.w, b = *(__half2*)&B.w;
                    __half2 c = *(__half2*)&C.w, e = *(__half2*)&E.w;
                    __half2 f = __hfma2(w10, b, __hmul2(w00, a));
                    f = __hfma2(w01, c, f);
                    f = __hfma2(w11, e, f);
                    R.w = *(unsigned*)&f;
                }

                float f[8]; H8F(R, f);
#pragma unroll
                for (int j = 0; j < 8; ++j) {
                    s[j] += f[j];
                    q[j] = fmaf(f[j], f[j], q[j]);
                }
            }

            const float inv3 = (1.0f/3.0f);
            float o[8];
#pragma unroll
            for (int j = 0; j < 8; ++j) {
                float m = s[j] * inv3;
                o[j] = q[j]*inv3 - m*m;
            }
            *(float4*)(s_var + w*36 + c4*8)     = make_float4(o[0], o[1], o[2], o[3]);
            *(float4*)(s_var + w*36 + c4*8 + 4) = make_float4(o[4], o[5], o[6], o[7]);
        }
    }
    __syncthreads();   // s_hwt/s_adr dead -> region becomes fold edges

    // zero fold-edge boundary cells (after union region is free)
    if (tid < 18) {
        int a  = tid / 9;
        int k9 = tid - a*9;
        if (a) s_e2[k9*162 + 160] = 0.0f;
        else   s_e0[k9*162 + 0]   = 0.0f;
    }

    // ---- Phase D: channel GEMM (FFMA2) + dx fold ----
    float S1[9];
    if (tid < WW) {
        int w = tid;
        ull va[16];
        const ulonglong2* qv = (const ulonglong2*)(s_var + w*36);
#pragma unroll
        for (int j = 0; j < 8; ++j) {
            ulonglong2 p = qv[j];
            va[2*j] = p.x; va[2*j+1] = p.y;
        }

#pragma unroll
        for (int k = 0; k < 27; ++k) {
            const ulonglong2* pw = (const ulonglong2*)(s_pwt + k*16);
            ull accA = 0ull, accB = 0ull;
#pragma unroll
            for (int c2 = 0; c2 < 8; ++c2) {
                ulonglong2 wp = pw[c2];
                FFMA2(accA, va[2*c2],   wp.x, accA);
                FFMA2(accB, va[2*c2+1], wp.y, accB);
            }
            float x0, x1, y0, y1;
            UNPACK2(x0, x1, accA);
            UNPACK2(y0, y1, accB);
            float S = (x0 + x1) + (y0 + y1);

            int k9 = k / 3, dx = k - k9*3;
            if (dx == 0)      s_e0[k9*162 + w + 1] = S;
            else if (dx == 1) S1[k9] = S;
            else              s_e2[k9*162 + w] = S;
        }
    }
    __syncthreads();

    if (tid < WW) {
        int w = tid;
        size_t base = (size_t)(d + 1)*SLICE + (h + 1)*ROWS + w;
#pragma unroll
        for (int k9 = 0; k9 < 9; ++k9) {
            float U = s_e0[k9*162 + w] + S1[k9] + s_e2[k9*162 + w + 1];
            g_S[(size_t)k9*CSTS + base] = U;
        }
    }
}

// ---------------------------------------------------------------------------
// Stage 3: 9-tap shifted-sum of partial volumes -> cost, 2x float4 per thread,
// 128-thread blocks for finer wave balance (960 blocks).
// ---------------------------------------------------------------------------
__global__ void __launch_bounds__(128)
sum_kernel()
{
    int idx = blockIdx.x * 128 + threadIdx.x;      // DD*HH*WW/8 = 122880
    int w8 = idx % 20;
    int t  = idx / 20;
    int h  = t % HH;
    int d  = t / HH;

    const float* base = g_S + (size_t)d*SLICE + h*ROWS + w8*8;
    float ax = 0.0f, ay = 0.0f, az = 0.0f, aw = 0.0f;
    float bx = 0.0f, by = 0.0f, bz = 0.0f, bw = 0.0f;
#pragma unroll
    for (int k9 = 0; k9 < 9; ++k9) {
        int dz = k9 / 3, dy = k9 - dz*3;
        const float* p = base + (size_t)k9*CSTS + dz*SLICE + dy*ROWS;
        float4 v0 = *(const float4*)p;
        float4 v1 = *(const float4*)(p + 4);
        ax += v0.x; ay += v0.y; az += v0.z; aw += v0.w;
        bx += v1.x; by += v1.y; bz += v1.z; bw += v1.w;
    }
    float* op = g_cost + d*HW + h*WW + w8*8;
    *(float4*)op       = make_float4(ax, ay, az, aw);
    *(float4*)(op + 4) = make_float4(bx, by, bz, bw);
}

// ---------------------------------------------------------------------------
// Stage 4: softmax over D, expected depth + max-prob confidence.
// ---------------------------------------------------------------------------
__global__ void __launch_bounds__(64)
depth_kernel(const float* __restrict__ depth_values, float* __restrict__ out)
{
    int pix = blockIdx.x * 64 + threadIdx.x;     // HW = 20480 exactly
    float cv[DD];
    float m = -1e30f;
#pragma unroll
    for (int d = 0; d < DD; ++d) {
        cv[d] = g_cost[d*HW + pix];
        m = fmaxf(m, cv[d]);
    }
    float sum = 0.0f, dep = 0.0f, best = 0.0f;
#pragma unroll
    for (int d = 0; d < DD; ++d) {
        float e = expf(cv[d] - m);
        sum += e;
        dep += e * __ldg(depth_values + d);
        best = fmaxf(best, e);
    }
    float isum = 1.0f / sum;
    out[pix]      = dep * isum;
    out[HW + pix] = best * isum;
}

// ---------------------------------------------------------------------------
extern "C" void kernel_launch(void* const* d_in, const int* in_sizes, int n_in,
                              void* d_out, int out_size)
{
    const float* feat0 = (const float*)d_in[0];
    const float* feat1 = (const float*)d_in[1];
    const float* feat2 = (const float*)d_in[2];
    const float* proj  = (const float*)d_in[3];
    const float* dvals = (const float*)d_in[4];
    const float* wreg  = (const float*)d_in[5];
    float* out = (float*)d_out;

    cudaFuncSetAttribute(warp_var_kernel,
                         cudaFuncAttributeMaxDynamicSharedMemorySize, SMEM_BYTES);

    prep_kernel<<<1, 1>>>(proj);
    transpose_kernel<<<dim3(HW/32, 3), dim3(32, 8)>>>(feat0, feat1, feat2);
    warp_var_kernel<<<DD*HH, 256, SMEM_BYTES>>>(dvals, wreg);
    sum_kernel<<<(DD*HH*WW/8)/128, 128>>>();
    depth_kernel<<<HW/64, 64>>>(dvals, out);
}

// round 17
// speedup vs baseline: 1.4236x; 1.0785x over previous
#include <cuda_runtime.h>
#include <cuda_bf16.h>
#include <cuda_fp16.h>
#include <math.h>

typedef unsigned long long ull;

// Problem constants
#define BB 1
#define CC 32
#define HH 128
#define WW 160
#define DD 48
#define HW (HH*WW)          // 20480

// Padded per-(dz,dy) partial volumes U: (9, D+2, H+2, W) — no w halo (dx folded)
#define PD (DD+2)           // 50
#define PH (HH+2)           // 130
#define ROWS   160
#define SLICE  (PH*ROWS)    // 20800
#define CSTS   (PD*SLICE)   // 1,040,000 per volume

// Device globals zero-initialized at module load; halo cells of g_S are never
// written, so SAME-padding zeros in d/h are free and persistent.
__device__ float g_rot[2][9];
__device__ float g_trans[2][3];
__device__ __half g_featTh[3][HW*CC];        // (view, y, x, c) channel-last fp16
__device__ float g_S[9u*CSTS];               // 9 padded partial volumes ~37MB
__device__ float g_cost[DD*HW];              // ~3.9 MB

#define FFMA2(d, a, b, c) \
    asm("fma.rn.f32x2 %0, %1, %2, %3;" : "=l"(d) : "l"(a), "l"(b), "l"(c))
#define PACK2(out, lo, hi) \
    asm("mov.b64 %0, {%1, %2};" : "=l"(out) : "f"(lo), "f"(hi))
#define UNPACK2(lo, hi, in) \
    asm("mov.b64 {%0, %1}, %2;" : "=f"(lo), "=f"(hi) : "l"(in))

// Dynamic smem layout (bytes).  Region [0,11664) is a UNION:
//   Phase A/B: s_hwt uint4[2][160] @0 (5120) | s_adr int4[2][160] @5120 (5120)
//   Phase D/E: s_e0 float[9][162] @0 (5832)  | s_e2 float[9][162] @5832 (5832)
#define OFF_HWT 0
#define OFF_ADR 5120
#define OFF_E0  0
#define OFF_E2  5832
#define OFF_VAR 11664          // float [160][36]  (23040 B; w stride 144B)
#define OFF_PWT 34704          // ull [27*16]      (3456 B)
#define SMEM_BYTES 38160

// Convert 8 packed halves (uint4) to 8 floats
__device__ __forceinline__ void H8F(uint4 u, float* f)
{
    float2 t0 = __half22float2(*(__half2*)&u.x);
    float2 t1 = __half22float2(*(__half2*)&u.y);
    float2 t2 = __half22float2(*(__half2*)&u.z);
    float2 t3 = __half22float2(*(__half2*)&u.w);
    f[0]=t0.x; f[1]=t0.y; f[2]=t1.x; f[3]=t1.y;
    f[4]=t2.x; f[5]=t2.y; f[6]=t3.x; f[7]=t3.y;
}

// Phase D worker: channel GEMM + dx-fold for k in [K0, K1) (k9-aligned range).
// Writes fold edges into the k9 rows it owns; accumulates dx==1 terms in S1.
template<int K0, int K1>
__device__ __forceinline__ void phaseD_range(
    const ull* va, const ull* s_pwt, float* s_e0, float* s_e2,
    int w, float* S1)
{
#pragma unroll
    for (int k = K0; k < K1; ++k) {
        const ulonglong2* pw = (const ulonglong2*)(s_pwt + k*16);
        ull accA = 0ull, accB = 0ull;
#pragma unroll
        for (int c2 = 0; c2 < 8; ++c2) {
            ulonglong2 wp = pw[c2];
            FFMA2(accA, va[2*c2],   wp.x, accA);
            FFMA2(accB, va[2*c2+1], wp.y, accB);
        }
        float x0, x1, y0, y1;
        UNPACK2(x0, x1, accA);
        UNPACK2(y0, y1, accB);
        float S = (x0 + x1) + (y0 + y1);

        int k9 = k / 3, dx = k - k9*3;
        if (dx == 0)      s_e0[k9*162 + w + 1] = S;
        else if (dx == 1) S1[k9 - K0/3] = S;
        else              s_e2[k9*162 + w] = S;
    }
}

// ---------------------------------------------------------------------------
// Stage 0: proj_v @ inv(proj_ref) -> rot(3x3), trans(3) for views 1,2
// ---------------------------------------------------------------------------
__global__ void prep_kernel(const float* __restrict__ proj)
{
    if (threadIdx.x != 0 || blockIdx.x != 0) return;
    float A0[9], b0[3];
    for (int r = 0; r < 3; ++r) {
        for (int c = 0; c < 3; ++c) A0[r*3+c] = proj[r*4+c];
        b0[r] = proj[r*4+3];
    }
    float inv[9];
    inv[0] =  A0[4]*A0[8] - A0[5]*A0[7];
    inv[1] = -(A0[1]*A0[8] - A0[2]*A0[7]);
    inv[2] =  A0[1]*A0[5] - A0[2]*A0[4];
    inv[3] = -(A0[3]*A0[8] - A0[5]*A0[6]);
    inv[4] =  A0[0]*A0[8] - A0[2]*A0[6];
    inv[5] = -(A0[0]*A0[5] - A0[2]*A0[3]);
    inv[6] =  A0[3]*A0[7] - A0[4]*A0[6];
    inv[7] = -(A0[0]*A0[7] - A0[1]*A0[6]);
    inv[8] =  A0[0]*A0[4] - A0[1]*A0[3];
    float det = A0[0]*inv[0] + A0[1]*inv[3] + A0[2]*inv[6];
    float idet = 1.0f / det;
    for (int i = 0; i < 9; ++i) inv[i] *= idet;

    for (int v = 1; v < 3; ++v) {
        const float* P = proj + v*16;
        float Av[9], bv[3];
        for (int r = 0; r < 3; ++r) {
            for (int c = 0; c < 3; ++c) Av[r*3+c] = P[r*4+c];
            bv[r] = P[r*4+3];
        }
        float rot[9];
        for (int r = 0; r < 3; ++r)
            for (int c = 0; c < 3; ++c)
                rot[r*3+c] = Av[r*3+0]*inv[0*3+c] + Av[r*3+1]*inv[1*3+c] + Av[r*3+2]*inv[2*3+c];
        for (int r = 0; r < 3; ++r)
            g_trans[v-1][r] = bv[r] - (rot[r*3+0]*b0[0] + rot[r*3+1]*b0[1] + rot[r*3+2]*b0[2]);
        for (int i = 0; i < 9; ++i) g_rot[v-1][i] = rot[i];
    }
}

// ---------------------------------------------------------------------------
// Stage 1: tiled transpose (C,H,W) -> (H,W,C) fp32 -> fp16 for all 3 views.
// ---------------------------------------------------------------------------
__global__ void transpose_kernel(const float* __restrict__ f0,
                                 const float* __restrict__ f1,
                                 const float* __restrict__ f2)
{
    __shared__ float t[32][33];
    int v  = blockIdx.y;
    int p0 = blockIdx.x * 32;
    int tx = threadIdx.x, ty = threadIdx.y;
    const float* src = (v == 0) ? f0 : (v == 1) ? f1 : f2;

#pragma unroll
    for (int j = ty; j < 32; j += 8)
        t[j][tx] = src[j*HW + p0 + tx];
    __syncthreads();
#pragma unroll
    for (int j = ty; j < 32; j += 8)
        g_featTh[v][(p0 + j)*CC + tx] = __float2half(t[tx][j]);
}

// ---------------------------------------------------------------------------
// Stage 2: warp + variance + fused channel GEMM + dx-fold (fp16 features).
// Block per (d,h), 320 threads, 38.2KB smem, 3 blocks/SM.
//  A: 640 coord items over 320 threads (2 iters).
//  B: 10 warps x 16 voxels: octet-voxel LDG.128 gathers + HFMA2 blend
//     (exactly 2 iters, no tail).
//  D: ALL 320 threads: tid<160 -> w=tid, k9 0..4; tid>=160 -> w=tid-160,
//     k9 5..8.  dx-fold is k9-local so the two groups are independent.
// ---------------------------------------------------------------------------
__global__ void __launch_bounds__(320, 3)
warp_var_kernel(const float* __restrict__ depth_values,
                const float* __restrict__ w_reg)
{
    extern __shared__ char smraw[];
    uint4*  s_hwt = (uint4*) (smraw + OFF_HWT);   // [v*160+w]: 4 dup'd half2
    int4*   s_adr = (int4*)  (smraw + OFF_ADR);   // pixel*4 (uint4 index)
    float*  s_var = (float*) (smraw + OFF_VAR);   // w*36 + c
    ull*    s_pwt = (ull*)   (smraw + OFF_PWT);   // k*16 + c2
    float*  s_e0  = (float*) (smraw + OFF_E0);    // k9*162 + idx
    float*  s_e2  = (float*) (smraw + OFF_E2);

    int blk = blockIdx.x;                  // 0 .. DD*HH-1
    int d = blk / HH;
    int h = blk - d*HH;
    int tid = threadIdx.x;

    float depth = __ldg(depth_values + d);

    // ---- Phase A: projection coords per (view, w) ----
    for (int t = tid; t < 2*WW; t += 320) {
        int v = t / WW;
        int w = t - v*WW;
        float fx = (float)w, fy = (float)h;

        float px = (g_rot[v][0]*fx + g_rot[v][1]*fy + g_rot[v][2]) * depth + g_trans[v][0];
        float py = (g_rot[v][3]*fx + g_rot[v][4]*fy + g_rot[v][5]) * depth + g_trans[v][1];
        float pz = (g_rot[v][6]*fx + g_rot[v][7]*fy + g_rot[v][8]) * depth + g_trans[v][2];
        float gx = __fdividef(px, pz);
        float gy = __fdividef(py, pz);

        float x0f = floorf(gx), y0f = floorf(gy);
        float wx = gx - x0f, wy = gy - y0f;
        float x1f = x0f + 1.0f, y1f = y0f + 1.0f;

        float vx0 = (x0f >= 0.0f && x0f <= (float)(WW-1)) ? 1.0f : 0.0f;
        float vx1 = (x1f >= 0.0f && x1f <= (float)(WW-1)) ? 1.0f : 0.0f;
        float vy0 = (y0f >= 0.0f && y0f <= (float)(HH-1)) ? 1.0f : 0.0f;
        float vy1 = (y1f >= 0.0f && y1f <= (float)(HH-1)) ? 1.0f : 0.0f;

        float w00 = (1.0f-wx)*(1.0f-wy) * (vx0*vy0);
        float w10 = wx*(1.0f-wy)        * (vx1*vy0);
        float w01 = (1.0f-wx)*wy        * (vx0*vy1);
        float w11 = wx*wy               * (vx1*vy1);

        int x0 = (int)fminf(fmaxf(x0f, 0.0f), (float)(WW-1));
        int x1 = (int)fminf(fmaxf(x1f, 0.0f), (float)(WW-1));
        int y0 = (int)fminf(fmaxf(y0f, 0.0f), (float)(HH-1));
        int y1 = (int)fminf(fmaxf(y1f, 0.0f), (float)(HH-1));

        __half2 h00 = __float2half2_rn(w00);
        __half2 h10 = __float2half2_rn(w10);
        __half2 h01 = __float2half2_rn(w01);
        __half2 h11 = __float2half2_rn(w11);
        uint4 hw;
        hw.x = *(unsigned*)&h00;
        hw.y = *(unsigned*)&h10;
        hw.z = *(unsigned*)&h01;
        hw.w = *(unsigned*)&h11;
        s_hwt[t] = hw;
        s_adr[t] = make_int4((y0*WW + x0)*4, (y0*WW + x1)*4,
                             (y1*WW + x0)*4, (y1*WW + x1)*4);
    }

    // Packed fp32 weights: s_pwt[k*16+c2] = (wt[2c2][k], wt[2c2+1][k])
    for (int i = tid; i < 27*16; i += 320) {
        int k  = i >> 4;
        int c2 = i & 15;
        float lo = __ldg(w_reg + (2*c2    )*27 + k);
        float hi = __ldg(w_reg + (2*c2 + 1)*27 + k);
        ull p; PACK2(p, lo, hi);
        s_pwt[i] = p;
    }
    __syncthreads();

    // ---- Phase B: octet-voxel fp16 gathers + HFMA2 blend + fp32 variance ----
    {
        int lane = tid & 31;
        int warp = tid >> 5;           // 0..9
        int qd   = lane >> 2;          // voxel within octet (0..7)
        int c4   = lane & 3;           // half8 channel group (0..3)

        const uint4* F0 = (const uint4*)g_featTh[0];
        const uint4* F1 = (const uint4*)g_featTh[1];
        const uint4* F2 = (const uint4*)g_featTh[2];

#pragma unroll
        for (int i = 0; i < 2; ++i) {
            int w = warp*16 + i*8 + qd;

            float s[8], q[8];
            {
                uint4 r = __ldg(F0 + (h*WW + w)*4 + c4);
                float f[8]; H8F(r, f);
#pragma unroll
                for (int j = 0; j < 8; ++j) { s[j] = f[j]; q[j] = f[j]*f[j]; }
            }

#pragma unroll
            for (int v = 0; v < 2; ++v) {
                const uint4* Fv = v ? F2 : F1;
                uint4 hw = s_hwt[v*160 + w];
                __half2 w00 = *(__half2*)&hw.x;
                __half2 w10 = *(__half2*)&hw.y;
                __half2 w01 = *(__half2*)&hw.z;
                __half2 w11 = *(__half2*)&hw.w;
                int4  ad = s_adr[v*160 + w];
                uint4 A = __ldg(Fv + ad.x + c4);
                uint4 B = __ldg(Fv + ad.y + c4);
                uint4 C = __ldg(Fv + ad.z + c4);
                uint4 E = __ldg(Fv + ad.w + c4);

                uint4 R;
                {
                    __half2 a = *(__half2*)&A.x, b = *(__half2*)&B.x;
                    __half2 c = *(__half2*)&C.x, e = *(__half2*)&E.x;
                    __half2 f = __hfma2(w10, b, __hmul2(w00, a));
                    f = __hfma2(w01, c, f);
                    f = __hfma2(w11, e, f);
                    R.x = *(unsigned*)&f;
                }
                {
                    __half2 a = *(__half2*)&A.y, b = *(__half2*)&B.y;
                    __half2 c = *(__half2*)&C.y, e = *(__half2*)&E.y;
                    __half2 f = __hfma2(w10, b, __hmul2(w00, a));
                    f = __hfma2(w01, c, f);
                    f = __hfma2(w11, e, f);
                    R.y = *(unsigned*)&f;
                }
                {
                    __half2 a = *(__half2*)&A.z, b = *(__half2*)&B.z;
                    __half2 c = *(__half2*)&C.z, e = *(__half2*)&E.z;
                    __half2 f = __hfma2(w10, b, __hmul2(w00, a));
                    f = __hfma2(w01, c, f);
                    f = __hfma2(w11, e, f);
                    R.z = *(unsigned*)&f;
                }
                {
                    __half2 a = *(__half2*)&A.w, b = *(__half2*)&B.w;
                    __half2 c = *(__half2*)&C.w, e = *(__half2*)&E.w;
                    __half2 f = __hfma2(w10, b, __hmul2(w00, a));
                    f = __hfma2(w01, c, f);
                    f = __hfma2(w11, e, f);
                    R.w = *(unsigned*)&f;
                }

                float f[8]; H8F(R, f);
#pragma unroll
                for (int j = 0; j < 8; ++j) {
                    s[j] += f[j];
                    q[j] = fmaf(f[j], f[j], q[j]);
                }
            }

            const float inv3 = (1.0f/3.0f);
            float o[8];
#pragma unroll
            for (int j = 0; j < 8; ++j) {
                float m = s[j] * inv3;
                o[j] = q[j]*inv3 - m*m;
            }
            *(float4*)(s_var + w*36 + c4*8)     = make_float4(o[0], o[1], o[2], o[3]);
            *(float4*)(s_var + w*36 + c4*8 + 4) = make_float4(o[4], o[5], o[6], o[7]);
        }
    }
    __syncthreads();   // s_hwt/s_adr dead -> region becomes fold edges

    // zero fold-edge boundary cells (after union region is free)
    if (tid < 18) {
        int a  = tid / 9;
        int k9 = tid - a*9;
        if (a) s_e2[k9*162 + 160] = 0.0f;
        else   s_e0[k9*162 + 0]   = 0.0f;
    }

    // ---- Phase D: k9-split channel GEMM across ALL 320 threads ----
    // group 0 (tid<160): w=tid,      k 0..14  (k9 0..4)
    // group 1 (tid>=160): w=tid-160, k 15..26 (k9 5..8)
    {
        int g = (tid >= 160);
        int w = g ? tid - 160 : tid;

        ull va[16];
        const ulonglong2* qv = (const ulonglong2*)(s_var + w*36);
#pragma unroll
        for (int j = 0; j < 8; ++j) {
            ulonglong2 p = qv[j];
            va[2*j] = p.x; va[2*j+1] = p.y;
        }

        float S1[5];
        if (!g) phaseD_range<0, 15>(va, s_pwt, s_e0, s_e2, w, S1);
        else    phaseD_range<15, 27>(va, s_pwt, s_e0, s_e2, w, S1);

        __syncthreads();

        size_t base = (size_t)(d + 1)*SLICE + (h + 1)*ROWS + w;
        if (!g) {
#pragma unroll
            for (int k9 = 0; k9 < 5; ++k9) {
                float U = s_e0[k9*162 + w] + S1[k9] + s_e2[k9*162 + w + 1];
                g_S[(size_t)k9*CSTS + base] = U;
            }
        } else {
#pragma unroll
            for (int k9 = 5; k9 < 9; ++k9) {
                float U = s_e0[k9*162 + w] + S1[k9 - 5] + s_e2[k9*162 + w + 1];
                g_S[(size_t)k9*CSTS + base] = U;
            }
        }
    }
}

// ---------------------------------------------------------------------------
// Stage 3: 9-tap shifted-sum of partial volumes -> cost, 2x float4 per thread.
// ---------------------------------------------------------------------------
__global__ void __launch_bounds__(128)
sum_kernel()
{
    int idx = blockIdx.x * 128 + threadIdx.x;      // DD*HH*WW/8 = 122880
    int w8 = idx % 20;
    int t  = idx / 20;
    int h  = t % HH;
    int d  = t / HH;

    const float* base = g_S + (size_t)d*SLICE + h*ROWS + w8*8;
    float ax = 0.0f, ay = 0.0f, az = 0.0f, aw = 0.0f;
    float bx = 0.0f, by = 0.0f, bz = 0.0f, bw = 0.0f;
#pragma unroll
    for (int k9 = 0; k9 < 9; ++k9) {
        int dz = k9 / 3, dy = k9 - dz*3;
        const float* p = base + (size_t)k9*CSTS + dz*SLICE + dy*ROWS;
        float4 v0 = *(const float4*)p;
        float4 v1 = *(const float4*)(p + 4);
        ax += v0.x; ay += v0.y; az += v0.z; aw += v0.w;
        bx += v1.x; by += v1.y; bz += v1.z; bw += v1.w;
    }
    float* op = g_cost + d*HW + h*WW + w8*8;
    *(float4*)op       = make_float4(ax, ay, az, aw);
    *(float4*)(op + 4) = make_float4(bx, by, bz, bw);
}

// ---------------------------------------------------------------------------
// Stage 4: softmax over D, expected depth + max-prob confidence.
// ---------------------------------------------------------------------------
__global__ void __launch_bounds__(64)
depth_kernel(const float* __restrict__ depth_values, float* __restrict__ out)
{
    int pix = blockIdx.x * 64 + threadIdx.x;     // HW = 20480 exactly
    float cv[DD];
    float m = -1e30f;
#pragma unroll
    for (int d = 0; d < DD; ++d) {
        cv[d] = g_cost[d*HW + pix];
        m = fmaxf(m, cv[d]);
    }
    float sum = 0.0f, dep = 0.0f, best = 0.0f;
#pragma unroll
    for (int d = 0; d < DD; ++d) {
        float e = expf(cv[d] - m);
        sum += e;
        dep += e * __ldg(depth_values + d);
        best = fmaxf(best, e);
    }
    float isum = 1.0f / sum;
    out[pix]      = dep * isum;
    out[HW + pix] = best * isum;
}

// ---------------------------------------------------------------------------
extern "C" void kernel_launch(void* const* d_in, const int* in_sizes, int n_in,
                              void* d_out, int out_size)
{
    const float* feat0 = (const float*)d_in[0];
    const float* feat1 = (const float*)d_in[1];
    const float* feat2 = (const float*)d_in[2];
    const float* proj  = (const float*)d_in[3];
    const float* dvals = (const float*)d_in[4];
    const float* wreg  = (const float*)d_in[5];
    float* out = (float*)d_out;

    cudaFuncSetAttribute(warp_var_kernel,
                         cudaFuncAttributeMaxDynamicSharedMemorySize, SMEM_BYTES);

    prep_kernel<<<1, 1>>>(proj);
    transpose_kernel<<<dim3(HW/32, 3), dim3(32, 8)>>>(feat0, feat1, feat2);
    warp_var_kernel<<<DD*HH, 320, SMEM_BYTES>>>(dvals, wreg);
    sum_kernel<<<(DD*HH*WW/8)/128, 128>>>();
    depth_kernel<<<HW/64, 64>>>(dvals, out);
}